// round 4
// baseline (speedup 1.0000x reference)
#include <cuda_runtime.h>
#include <cuda_bf16.h>
#include <math.h>
#include <stdint.h>

#define NN 512
#define CC 3
#define PIX 1024
#define FF 3072          // K dim
#define HH 4
#define HF 12288         // N dim
#define EE 4096
#define ET 4608
#define BEPS 1e-5f
#define SLOPE 0.2f

// GEMM tiling
#define BM 128
#define BN 128
#define BK 32
#define NK (FF / BK)             // 96
#define TILES_PER_GEMM ((NN / BM) * (HF / BN))   // 384

// smem layout
#define A_STRIDE 80              // 32 bf16 -> 64 B + 16 pad
#define B_STRIDE 272             // 128 bf16 -> 256 B + 16 pad
#define A_STAGE_BYTES (2 * BM * A_STRIDE)        // hi + lo = 20480
#define OFF_ALO (BM * A_STRIDE)                  // 10240
#define OFF_B (3 * A_STAGE_BYTES)                // 61440
#define B_HALF (BK * B_STRIDE)                   // 8704
#define B_BUF_BYTES (2 * B_HALF)                 // 17408 (hi+lo)
#define SMEM_TOTAL (OFF_B + 2 * B_BUF_BYTES)     // 96256

// ---------------- scratch ----------------------------------------------------
__device__ __nv_bfloat16 d_Ah[NN * FF];
__device__ __nv_bfloat16 d_Al[NN * FF];
__device__ float d_xl[(size_t)NN * HF];
__device__ float d_xr[(size_t)NN * HF];
__device__ float d_logits[ET * HH];
__device__ float d_mx[NN * HH];
__device__ float d_den[NN * HH];
__device__ float d_alpha[ET * HH];
__device__ float d_agg[(size_t)NN * HF];
__device__ int   d_deg[NN];
__device__ int   d_rowptr[NN + 1];
__device__ int   d_cursor[NN];
__device__ int   d_elist[ET];
__device__ int   d_esrc[ET];

// ---------------- PTX helpers ------------------------------------------------
__device__ __forceinline__ uint32_t smem_to_u32(const void* p) {
    uint32_t a;
    asm("{ .reg .u64 t; cvta.to.shared.u64 t, %1; cvt.u32.u64 %0, t; }" : "=r"(a) : "l"(p));
    return a;
}
__device__ __forceinline__ void cpa16(uint32_t dst, const void* src) {
    asm volatile("cp.async.cg.shared.global [%0], [%1], 16;" :: "r"(dst), "l"(src));
}
#define CP_COMMIT() asm volatile("cp.async.commit_group;" ::: "memory")
#define CP_WAIT0()  asm volatile("cp.async.wait_group 0;" ::: "memory")
#define CP_WAIT1()  asm volatile("cp.async.wait_group 1;" ::: "memory")

#define LDSM_X4(r0, r1, r2, r3, addr) \
    asm volatile("ldmatrix.sync.aligned.m8n8.x4.shared.b16 {%0,%1,%2,%3}, [%4];" \
        : "=r"(r0), "=r"(r1), "=r"(r2), "=r"(r3) : "r"(addr))
#define LDSM_X4T(r0, r1, r2, r3, addr) \
    asm volatile("ldmatrix.sync.aligned.m8n8.x4.trans.shared.b16 {%0,%1,%2,%3}, [%4];" \
        : "=r"(r0), "=r"(r1), "=r"(r2), "=r"(r3) : "r"(addr))

#define MMA16816(d, a, b) \
    asm volatile("mma.sync.aligned.m16n8k16.row.col.f32.bf16.bf16.f32 " \
        "{%0,%1,%2,%3}, {%4,%5,%6,%7}, {%8,%9}, {%0,%1,%2,%3};" \
        : "+f"((d)[0]), "+f"((d)[1]), "+f"((d)[2]), "+f"((d)[3]) \
        : "r"((a)[0]), "r"((a)[1]), "r"((a)[2]), "r"((a)[3]), "r"((b)[0]), "r"((b)[1]))

#define STS128(addr, r0, r1, r2, r3) \
    asm volatile("st.shared.v4.b32 [%0], {%1,%2,%3,%4};" \
        :: "r"(addr), "r"(r0), "r"(r1), "r"(r2), "r"(r3) : "memory")

__device__ __forceinline__ uint32_t packbf2(float x, float y) {
    uint32_t r;
    asm("cvt.rn.bf16x2.f32 %0, %1, %2;" : "=r"(r) : "f"(y), "f"(x));  // low=x, high=y
    return r;
}

// ---------------- misc helpers ----------------------------------------------
__device__ __forceinline__ void atomicMaxF(float* addr, float val) {
    if (val >= 0.0f) atomicMax((int*)addr, __float_as_int(val));
    else             atomicMin((unsigned int*)addr, __float_as_uint(val));
}
__device__ __forceinline__ int edge_src(const int* ei, int e) { return (e < EE) ? ei[e] : (e - EE); }
__device__ __forceinline__ int edge_dst(const int* ei, int e) { return (e < EE) ? ei[EE + e] : (e - EE); }

// ---------------- stage 1: fc1 + BN1 -> bf16 hi/lo ---------------------------
__global__ void fc1_bn_kernel(const float* __restrict__ x,
                              const float* __restrict__ W,
                              const float* __restrict__ b,
                              const float* __restrict__ bg,
                              const float* __restrict__ bb,
                              const float* __restrict__ bm,
                              const float* __restrict__ bv) {
    int n = blockIdx.x;
    int p = blockIdx.y * 256 + threadIdx.x;
    float xin[CC];
#pragma unroll
    for (int c = 0; c < CC; c++) xin[c] = x[(size_t)n * FF + c * PIX + p];
#pragma unroll
    for (int oc = 0; oc < CC; oc++) {
        float t = b[oc];
#pragma unroll
        for (int ic = 0; ic < CC; ic++) t += W[oc * CC + ic] * xin[ic];
        float inv = bg[oc] * rsqrtf(bv[oc] + BEPS);
        float hv = t * inv + bb[oc] - bm[oc] * inv;
        __nv_bfloat16 hi = __float2bfloat16(hv);
        size_t o = (size_t)n * FF + oc * PIX + p;
        d_Ah[o] = hi;
        d_Al[o] = __float2bfloat16(hv - __bfloat162float(hi));
    }
}

// ---------------- init small state -------------------------------------------
__global__ void init_kernel() {
    int i = blockIdx.x * blockDim.x + threadIdx.x;
    if (i < NN * HH) { d_mx[i] = -INFINITY; d_den[i] = 0.0f; }
    if (i < NN) d_deg[i] = 0;
}

// ---------------- stage 2: HMMA GEMM with in-kernel B split ------------------
__device__ __forceinline__ void load_stage_A(uint32_t st, int m0, int k0, int tid) {
#pragma unroll
    for (int i = tid; i < 512; i += 256) {
        int row = i >> 2, c = i & 3;
        uint32_t off = row * A_STRIDE + c * 16;
        size_t g = (size_t)(m0 + row) * FF + k0 + c * 8;
        cpa16(st + off, d_Ah + g);
        cpa16(st + OFF_ALO + off, d_Al + g);
    }
}

__global__ void __launch_bounds__(256)
mmagemm_kernel(const float* __restrict__ Wl, const float* __restrict__ Wr,
               const float* __restrict__ biasL, const float* __restrict__ biasR) {
    extern __shared__ __align__(1024) char smem[];
    uint32_t sbase = smem_to_u32(smem);
    int tid = threadIdx.x;
    int wid = tid >> 5, lane = tid & 31;

    int bid = blockIdx.x;
    int gemm = (bid >= TILES_PER_GEMM) ? 1 : 0;
    int r = bid - gemm * TILES_PER_GEMM;
    int n0 = (r >> 2) * BN;
    int m0 = (r & 3) * BM;

    const float* W = gemm ? Wr : Wl;
    const float* bias = gemm ? biasR : biasL;
    float* C = gemm ? d_xr : d_xl;

    int wm = (wid & 1) * 64;
    int wn = (wid >> 1) * 32;

    uint32_t stgA[3] = { sbase, sbase + A_STAGE_BYTES, sbase + 2 * A_STAGE_BYTES };
    uint32_t bbuf[2] = { sbase + OFF_B, sbase + OFF_B + B_BUF_BYTES };

    float acc[4][4][4];
#pragma unroll
    for (int mf = 0; mf < 4; mf++)
#pragma unroll
        for (int nf = 0; nf < 4; nf++)
#pragma unroll
            for (int q = 0; q < 4; q++) acc[mf][nf][q] = 0.0f;

    // B global mapping: thread -> (k-row, 16-col group)
    int bkr = tid >> 3, bg = tid & 7;
    const float* bptr = W + (size_t)bkr * HF + n0 + bg * 16;
    uint32_t bsoff = bkr * B_STRIDE + bg * 32;

    // prologue
    load_stage_A(stgA[0], m0, 0, tid);
    CP_COMMIT();
    load_stage_A(stgA[1], m0, BK, tid);
    CP_COMMIT();
    float4 br4[4];
#pragma unroll
    for (int q = 0; q < 4; q++) br4[q] = *((const float4*)bptr + q);

    uint32_t a_lrow = (lane & 7) + ((lane >> 3) & 1) * 8;
    uint32_t a_kadd = (lane >> 4) * 16;
    uint32_t b_lrow = (lane & 7) + ((lane >> 3) & 1) * 8;
    uint32_t b_nadd = (lane >> 4) * 16;

    for (int kt = 0; kt < NK; kt++) {
        if (kt + 2 < NK) { CP_WAIT1(); } else { CP_WAIT0(); }

        // convert held B chunk -> bf16 hi/lo smem buffer (kt&1)
        {
            uint32_t h[8], l[8];
#pragma unroll
            for (int q = 0; q < 4; q++) {
                float4 v = br4[q];
                __nv_bfloat16 bx = __float2bfloat16(v.x);
                __nv_bfloat16 by = __float2bfloat16(v.y);
                __nv_bfloat16 bz = __float2bfloat16(v.z);
                __nv_bfloat16 bw = __float2bfloat16(v.w);
                h[2 * q]     = packbf2(__bfloat162float(bx), __bfloat162float(by));
                h[2 * q + 1] = packbf2(__bfloat162float(bz), __bfloat162float(bw));
                l[2 * q]     = packbf2(v.x - __bfloat162float(bx), v.y - __bfloat162float(by));
                l[2 * q + 1] = packbf2(v.z - __bfloat162float(bz), v.w - __bfloat162float(bw));
            }
            uint32_t ah = bbuf[kt & 1] + bsoff;
            STS128(ah,      h[0], h[1], h[2], h[3]);
            STS128(ah + 16, h[4], h[5], h[6], h[7]);
            STS128(ah + B_HALF,      l[0], l[1], l[2], l[3]);
            STS128(ah + B_HALF + 16, l[4], l[5], l[6], l[7]);
        }
        // prefetch next B chunk into regs
        if (kt + 1 < NK) {
            const float* p = bptr + (size_t)(kt + 1) * BK * HF;
#pragma unroll
            for (int q = 0; q < 4; q++) br4[q] = *((const float4*)p + q);
        }
        __syncthreads();
        if (kt + 2 < NK) {
            load_stage_A(stgA[(kt + 2) % 3], m0, (kt + 2) * BK, tid);
            CP_COMMIT();
        }

        uint32_t st = stgA[kt % 3];
        uint32_t bb = bbuf[kt & 1];
#pragma unroll
        for (int kk = 0; kk < BK; kk += 16) {
            uint32_t ahi[4][4], alo[4][4], bhi[4][2], blo[4][2];
            uint32_t abase = st + (wm + a_lrow) * A_STRIDE + kk * 2 + a_kadd;
#pragma unroll
            for (int mf = 0; mf < 4; mf++) {
                uint32_t ad = abase + mf * 16 * A_STRIDE;
                LDSM_X4(ahi[mf][0], ahi[mf][1], ahi[mf][2], ahi[mf][3], ad);
                LDSM_X4(alo[mf][0], alo[mf][1], alo[mf][2], alo[mf][3], ad + OFF_ALO);
            }
            uint32_t bbase = bb + (kk + b_lrow) * B_STRIDE + wn * 2 + b_nadd;
            LDSM_X4T(bhi[0][0], bhi[0][1], bhi[1][0], bhi[1][1], bbase);
            LDSM_X4T(bhi[2][0], bhi[2][1], bhi[3][0], bhi[3][1], bbase + 32);
            LDSM_X4T(blo[0][0], blo[0][1], blo[1][0], blo[1][1], bbase + B_HALF);
            LDSM_X4T(blo[2][0], blo[2][1], blo[3][0], blo[3][1], bbase + B_HALF + 32);
#pragma unroll
            for (int mf = 0; mf < 4; mf++)
#pragma unroll
                for (int nf = 0; nf < 4; nf++) {
                    MMA16816(acc[mf][nf], ahi[mf], bhi[nf]);
                    MMA16816(acc[mf][nf], ahi[mf], blo[nf]);
                    MMA16816(acc[mf][nf], alo[mf], bhi[nf]);
                }
        }
    }

    // epilogue
    int g = lane >> 2, tc = lane & 3;
#pragma unroll
    for (int mf = 0; mf < 4; mf++) {
#pragma unroll
        for (int nf = 0; nf < 4; nf++) {
            int row = m0 + wm + mf * 16 + g;
            int col = n0 + wn + nf * 8 + tc * 2;
            float b0 = bias[col], b1 = bias[col + 1];
            float2 v0 = make_float2(acc[mf][nf][0] + b0, acc[mf][nf][1] + b1);
            float2 v1 = make_float2(acc[mf][nf][2] + b0, acc[mf][nf][3] + b1);
            *(float2*)(C + (size_t)row * HF + col) = v0;
            *(float2*)(C + (size_t)(row + 8) * HF + col) = v1;
        }
    }
}

// ---------------- stage 3: edge logits + degree + segment max ----------------
__global__ void logits_kernel(const int* __restrict__ ei, const float* __restrict__ att) {
    int e    = blockIdx.x;
    int h    = threadIdx.x >> 5;
    int lane = threadIdx.x & 31;
    int src = edge_src(ei, e);
    int dst = edge_dst(ei, e);
    if (threadIdx.x == 0) atomicAdd(&d_deg[dst], 1);
    const float4* pl = (const float4*)(d_xl + (size_t)src * HF + h * FF);
    const float4* pr = (const float4*)(d_xr + (size_t)dst * HF + h * FF);
    const float4* pa = (const float4*)(att + h * FF);
    float s = 0.0f;
#pragma unroll 4
    for (int it = 0; it < 24; it++) {
        int idx = lane + it * 32;
        float4 a = pl[idx];
        float4 b = pr[idx];
        float4 w = pa[idx];
        float z;
        z = a.x + b.x; s += w.x * (z > 0.0f ? z : SLOPE * z);
        z = a.y + b.y; s += w.y * (z > 0.0f ? z : SLOPE * z);
        z = a.z + b.z; s += w.z * (z > 0.0f ? z : SLOPE * z);
        z = a.w + b.w; s += w.w * (z > 0.0f ? z : SLOPE * z);
    }
#pragma unroll
    for (int o = 16; o; o >>= 1) s += __shfl_xor_sync(0xFFFFFFFFu, s, o);
    if (lane == 0) {
        d_logits[e * HH + h] = s;
        atomicMaxF(&d_mx[dst * HH + h], s);
    }
}

// ---------------- stage 4: exp + denom (alpha left unnormalized) -------------
__global__ void segexp_kernel(const int* __restrict__ ei) {
    int i = blockIdx.x * blockDim.x + threadIdx.x;
    if (i >= ET * HH) return;
    int e = i >> 2, h = i & 3;
    int dst = edge_dst(ei, e);
    float ex = expf(d_logits[i] - d_mx[dst * HH + h]);
    d_alpha[i] = ex;
    atomicAdd(&d_den[dst * HH + h], ex);
}

// ---------------- CSR build (by dst) -----------------------------------------
__global__ void scan_kernel() {
    __shared__ int s[NN];
    int t = threadIdx.x;
    s[t] = d_deg[t];
    __syncthreads();
    for (int o = 1; o < NN; o <<= 1) {
        int v = (t >= o) ? s[t - o] : 0;
        __syncthreads();
        s[t] += v;
        __syncthreads();
    }
    if (t == 0) d_rowptr[0] = 0;
    d_rowptr[t + 1] = s[t];
    d_cursor[t] = s[t] - d_deg[t];
}
__global__ void scatter_kernel(const int* __restrict__ ei) {
    int e = blockIdx.x * blockDim.x + threadIdx.x;
    if (e >= ET) return;
    int slot = atomicAdd(&d_cursor[edge_dst(ei, e)], 1);
    d_elist[slot] = e;
    d_esrc[slot] = edge_src(ei, e);
}

// ---------------- stage 5: aggregation (smem edge cache, denom folded) -------
__global__ void __launch_bounds__(256)
agg_kernel() {
    __shared__ int   s_src[128];
    __shared__ float s_al[HH][128];
    __shared__ float s_inv[HH];
    int n = blockIdx.x, tid = threadIdx.x;
    int s0 = d_rowptr[n], s1 = d_rowptr[n + 1];
    if (tid < HH) s_inv[tid] = 1.0f / d_den[n * HH + tid];

    float4 acc[12];
#pragma unroll
    for (int j = 0; j < 12; j++) acc[j] = make_float4(0.f, 0.f, 0.f, 0.f);

    for (int base = s0; base < s1; base += 128) {
        int cnt = min(128, s1 - base);
        __syncthreads();
        if (tid < cnt) {
            int e = d_elist[base + tid];
            s_src[tid] = d_esrc[base + tid];
            float4 a = *(const float4*)(d_alpha + e * HH);
            s_al[0][tid] = a.x; s_al[1][tid] = a.y;
            s_al[2][tid] = a.z; s_al[3][tid] = a.w;
        }
        __syncthreads();
        for (int s = 0; s < cnt; s++) {
            const float4* row = (const float4*)(d_xl + (size_t)s_src[s] * HF);
            float al0 = s_al[0][s], al1 = s_al[1][s], al2 = s_al[2][s], al3 = s_al[3][s];
#pragma unroll
            for (int j = 0; j < 12; j++) {
                float al = (j < 3) ? al0 : (j < 6) ? al1 : (j < 9) ? al2 : al3;
                float4 v = row[j * 256 + tid];
                acc[j].x += al * v.x;
                acc[j].y += al * v.y;
                acc[j].z += al * v.z;
                acc[j].w += al * v.w;
            }
        }
    }

#pragma unroll
    for (int j = 0; j < 12; j++) {
        float inv = s_inv[j / 3];
        float4 v = make_float4(acc[j].x * inv, acc[j].y * inv, acc[j].z * inv, acc[j].w * inv);
        *(float4*)(d_agg + (size_t)n * HF + (j * 256 + tid) * 4) = v;
    }
}

// ---------------- stage 6: fc2+BN2+residual + FFN (fused) --------------------
__global__ void final_kernel(const float* __restrict__ x,
                             const float* __restrict__ gat_b,
                             const float* __restrict__ fc2W, const float* __restrict__ fc2b,
                             const float* __restrict__ b2g, const float* __restrict__ b2b,
                             const float* __restrict__ b2m, const float* __restrict__ b2v,
                             const float* __restrict__ f1W, const float* __restrict__ f1b,
                             const float* __restrict__ bf1g, const float* __restrict__ bf1b,
                             const float* __restrict__ bf1m, const float* __restrict__ bf1v,
                             const float* __restrict__ f2W, const float* __restrict__ f2b,
                             const float* __restrict__ bf2g, const float* __restrict__ bf2b,
                             const float* __restrict__ bf2m, const float* __restrict__ bf2v,
                             float* __restrict__ out) {
    int n = blockIdx.x;
    int p = blockIdx.y * 256 + threadIdx.x;

    float ch[HH * CC];
#pragma unroll
    for (int h = 0; h < HH; h++)
#pragma unroll
        for (int c = 0; c < CC; c++)
            ch[h * CC + c] = d_agg[(size_t)n * HF + h * FF + c * PIX + p]
                           + gat_b[h * FF + c * PIX + p];

    float gv[CC];
#pragma unroll
    for (int oc = 0; oc < CC; oc++) {
        float t = fc2b[oc];
#pragma unroll
        for (int k = 0; k < HH * CC; k++) t += fc2W[oc * (HH * CC) + k] * ch[k];
        float inv = b2g[oc] * rsqrtf(b2v[oc] + BEPS);
        gv[oc] = t * inv + b2b[oc] - b2m[oc] * inv + x[(size_t)n * FF + oc * PIX + p];
    }
    float f1[CC];
#pragma unroll
    for (int oc = 0; oc < CC; oc++) {
        float t = f1b[oc];
#pragma unroll
        for (int ic = 0; ic < CC; ic++) t += f1W[oc * CC + ic] * gv[ic];
        float inv = bf1g[oc] * rsqrtf(bf1v[oc] + BEPS);
        float val = t * inv + bf1b[oc] - bf1m[oc] * inv;
        f1[oc] = val > 0.0f ? val : 0.0f;
    }
#pragma unroll
    for (int oc = 0; oc < CC; oc++) {
        float t = f2b[oc];
#pragma unroll
        for (int ic = 0; ic < CC; ic++) t += f2W[oc * CC + ic] * f1[ic];
        float inv = bf2g[oc] * rsqrtf(bf2v[oc] + BEPS);
        float val = t * inv + bf2b[oc] - bf2m[oc] * inv;
        out[(size_t)n * FF + oc * PIX + p] = val + gv[oc];
    }
}

// ---------------- launch -----------------------------------------------------
extern "C" void kernel_launch(void* const* d_in, const int* in_sizes, int n_in,
                              void* d_out, int out_size) {
    const float* x     = (const float*)d_in[0];
    const int*   ei    = (const int*)d_in[1];
    const float* fc1W  = (const float*)d_in[2];
    const float* fc1b  = (const float*)d_in[3];
    const float* b1g   = (const float*)d_in[4];
    const float* b1b   = (const float*)d_in[5];
    const float* b1m   = (const float*)d_in[6];
    const float* b1v   = (const float*)d_in[7];
    const float* Wl    = (const float*)d_in[8];
    const float* bl    = (const float*)d_in[9];
    const float* Wr    = (const float*)d_in[10];
    const float* br    = (const float*)d_in[11];
    const float* att   = (const float*)d_in[12];
    const float* gat_b = (const float*)d_in[13];
    const float* fc2W  = (const float*)d_in[14];
    const float* fc2b  = (const float*)d_in[15];
    const float* b2g   = (const float*)d_in[16];
    const float* b2b   = (const float*)d_in[17];
    const float* b2m   = (const float*)d_in[18];
    const float* b2v   = (const float*)d_in[19];
    const float* f1W   = (const float*)d_in[20];
    const float* f1b   = (const float*)d_in[21];
    const float* bf1g  = (const float*)d_in[22];
    const float* bf1b  = (const float*)d_in[23];
    const float* bf1m  = (const float*)d_in[24];
    const float* bf1v  = (const float*)d_in[25];
    const float* f2W   = (const float*)d_in[26];
    const float* f2b   = (const float*)d_in[27];
    const float* bf2g  = (const float*)d_in[28];
    const float* bf2b  = (const float*)d_in[29];
    const float* bf2m  = (const float*)d_in[30];
    const float* bf2v  = (const float*)d_in[31];
    float* out = (float*)d_out;

    cudaFuncSetAttribute(mmagemm_kernel, cudaFuncAttributeMaxDynamicSharedMemorySize, SMEM_TOTAL);

    fc1_bn_kernel<<<dim3(NN, 4), 256>>>(x, fc1W, fc1b, b1g, b1b, b1m, b1v);
    init_kernel<<<8, 256>>>();
    mmagemm_kernel<<<2 * TILES_PER_GEMM, 256, SMEM_TOTAL>>>(Wl, Wr, bl, br);
    logits_kernel<<<ET, 128>>>(ei, att);
    segexp_kernel<<<(ET * HH + 255) / 256, 256>>>(ei);
    scan_kernel<<<1, NN>>>();
    scatter_kernel<<<(ET + 255) / 256, 256>>>(ei);
    agg_kernel<<<NN, 256>>>();
    final_kernel<<<dim3(NN, 4), 256>>>(x, gat_b, fc2W, fc2b, b2g, b2b, b2m, b2v,
                                       f1W, f1b, bf1g, bf1b, bf1m, bf1v,
                                       f2W, f2b, bf2g, bf2b, bf2m, bf2v, out);
}

// round 5
// speedup vs baseline: 1.0093x; 1.0093x over previous
#include <cuda_runtime.h>
#include <cuda_bf16.h>
#include <math.h>
#include <stdint.h>

#define NN 512
#define CC 3
#define PIX 1024
#define FF 3072          // K dim
#define HH 4
#define HF 12288         // N dim
#define EE 4096
#define ET 4608
#define BEPS 1e-5f
#define SLOPE 0.2f

// GEMM tiling
#define BM 128
#define BN 128
#define BK 32
#define NK (FF / BK)             // 96
#define TILES_PER_GEMM ((NN / BM) * (HF / BN))   // 384

// smem stage layout (bf16, padded rows for conflict-free ldmatrix)
#define A_STRIDE 80
#define B_STRIDE 272
#define OFF_AHI 0
#define OFF_ALO (BM * A_STRIDE)                  // 10240
#define OFF_BHI (2 * BM * A_STRIDE)              // 20480
#define OFF_BLO (OFF_BHI + BK * B_STRIDE)        // 29184
#define STAGE_BYTES (OFF_BLO + BK * B_STRIDE)    // 37888
#define SMEM_TOTAL (2 * STAGE_BYTES)             // 75776 -> 2 CTAs/SM

// logits kernel smem: xr cache + logits buffer
#define LS_CAP 128
#define LS_SMEM (HF * 4 + HH * LS_CAP * 4)       // 49152 + 2048 = 51200

// ---------------- scratch ----------------------------------------------------
__device__ __nv_bfloat16 d_Ah[NN * FF];
__device__ __nv_bfloat16 d_Al[NN * FF];
__device__ __nv_bfloat16 d_Blh[(size_t)FF * HF];
__device__ __nv_bfloat16 d_Bll[(size_t)FF * HF];
__device__ __nv_bfloat16 d_Brh[(size_t)FF * HF];
__device__ __nv_bfloat16 d_Brl[(size_t)FF * HF];
__device__ float d_xl[(size_t)NN * HF];
__device__ float d_xr[(size_t)NN * HF];
__device__ float d_alpha[ET * HH];
__device__ float d_agg[(size_t)NN * HF];
__device__ int   d_deg[NN];
__device__ int   d_rowptr[NN + 1];
__device__ int   d_cursor[NN];
__device__ int   d_esrc[ET];

// ---------------- PTX helpers ------------------------------------------------
__device__ __forceinline__ uint32_t smem_to_u32(const void* p) {
    uint32_t a;
    asm("{ .reg .u64 t; cvta.to.shared.u64 t, %1; cvt.u32.u64 %0, t; }" : "=r"(a) : "l"(p));
    return a;
}
__device__ __forceinline__ void cpa16(uint32_t dst, const void* src) {
    asm volatile("cp.async.cg.shared.global [%0], [%1], 16;" :: "r"(dst), "l"(src));
}
#define CP_COMMIT() asm volatile("cp.async.commit_group;" ::: "memory")
#define CP_WAIT0()  asm volatile("cp.async.wait_group 0;" ::: "memory")
#define CP_WAIT1()  asm volatile("cp.async.wait_group 1;" ::: "memory")

#define LDSM_X4(r0, r1, r2, r3, addr) \
    asm volatile("ldmatrix.sync.aligned.m8n8.x4.shared.b16 {%0,%1,%2,%3}, [%4];" \
        : "=r"(r0), "=r"(r1), "=r"(r2), "=r"(r3) : "r"(addr))
#define LDSM_X4T(r0, r1, r2, r3, addr) \
    asm volatile("ldmatrix.sync.aligned.m8n8.x4.trans.shared.b16 {%0,%1,%2,%3}, [%4];" \
        : "=r"(r0), "=r"(r1), "=r"(r2), "=r"(r3) : "r"(addr))

#define MMA16816(d, a, b) \
    asm volatile("mma.sync.aligned.m16n8k16.row.col.f32.bf16.bf16.f32 " \
        "{%0,%1,%2,%3}, {%4,%5,%6,%7}, {%8,%9}, {%0,%1,%2,%3};" \
        : "+f"((d)[0]), "+f"((d)[1]), "+f"((d)[2]), "+f"((d)[3]) \
        : "r"((a)[0]), "r"((a)[1]), "r"((a)[2]), "r"((a)[3]), "r"((b)[0]), "r"((b)[1]))

// ---------------- misc -------------------------------------------------------
__device__ __forceinline__ int edge_src(const int* ei, int e) { return (e < EE) ? ei[e] : (e - EE); }
__device__ __forceinline__ int edge_dst(const int* ei, int e) { return (e < EE) ? ei[EE + e] : (e - EE); }

// ---------------- stage 1: fc1 + BN1 -> bf16 hi/lo ---------------------------
__global__ void fc1_bn_kernel(const float* __restrict__ x,
                              const float* __restrict__ W,
                              const float* __restrict__ b,
                              const float* __restrict__ bg,
                              const float* __restrict__ bb,
                              const float* __restrict__ bm,
                              const float* __restrict__ bv) {
    int n = blockIdx.x;
    int p = blockIdx.y * 256 + threadIdx.x;
    float xin[CC];
#pragma unroll
    for (int c = 0; c < CC; c++) xin[c] = x[(size_t)n * FF + c * PIX + p];
#pragma unroll
    for (int oc = 0; oc < CC; oc++) {
        float t = b[oc];
#pragma unroll
        for (int ic = 0; ic < CC; ic++) t += W[oc * CC + ic] * xin[ic];
        float inv = bg[oc] * rsqrtf(bv[oc] + BEPS);
        float hv = t * inv + bb[oc] - bm[oc] * inv;
        __nv_bfloat16 hi = __float2bfloat16(hv);
        size_t o = (size_t)n * FF + oc * PIX + p;
        d_Ah[o] = hi;
        d_Al[o] = __float2bfloat16(hv - __bfloat162float(hi));
    }
}

// ---------------- weight bf16 hi/lo split (streaming) ------------------------
__global__ void wsplit_kernel(const float* __restrict__ Wl, const float* __restrict__ Wr) {
    const float* W = blockIdx.y ? Wr : Wl;
    __nv_bfloat16* Bh = blockIdx.y ? d_Brh : d_Blh;
    __nv_bfloat16* Bl = blockIdx.y ? d_Brl : d_Bll;
    size_t i = ((size_t)blockIdx.x * 256 + threadIdx.x) * 4;
    float4 v = *(const float4*)(W + i);
    __nv_bfloat16 h0 = __float2bfloat16(v.x);
    __nv_bfloat16 h1 = __float2bfloat16(v.y);
    __nv_bfloat16 h2 = __float2bfloat16(v.z);
    __nv_bfloat16 h3 = __float2bfloat16(v.w);
    __nv_bfloat162* ph = (__nv_bfloat162*)(Bh + i);
    ph[0] = __nv_bfloat162(h0, h1);
    ph[1] = __nv_bfloat162(h2, h3);
    __nv_bfloat162* pl = (__nv_bfloat162*)(Bl + i);
    pl[0] = __nv_bfloat162(__float2bfloat16(v.x - __bfloat162float(h0)),
                           __float2bfloat16(v.y - __bfloat162float(h1)));
    pl[1] = __nv_bfloat162(__float2bfloat16(v.z - __bfloat162float(h2)),
                           __float2bfloat16(v.w - __bfloat162float(h3)));
}

// ---------------- init -------------------------------------------------------
__global__ void init_kernel() {
    int i = blockIdx.x * blockDim.x + threadIdx.x;
    if (i < NN) d_deg[i] = 0;
}

// ---------------- CSR build (by dst) -----------------------------------------
__global__ void deg_kernel(const int* __restrict__ ei) {
    int e = blockIdx.x * blockDim.x + threadIdx.x;
    if (e >= ET) return;
    atomicAdd(&d_deg[edge_dst(ei, e)], 1);
}
__global__ void scan_kernel() {
    __shared__ int s[NN];
    int t = threadIdx.x;
    s[t] = d_deg[t];
    __syncthreads();
    for (int o = 1; o < NN; o <<= 1) {
        int v = (t >= o) ? s[t - o] : 0;
        __syncthreads();
        s[t] += v;
        __syncthreads();
    }
    if (t == 0) d_rowptr[0] = 0;
    d_rowptr[t + 1] = s[t];
    d_cursor[t] = s[t] - d_deg[t];
}
__global__ void scatter_kernel(const int* __restrict__ ei) {
    int e = blockIdx.x * blockDim.x + threadIdx.x;
    if (e >= ET) return;
    int slot = atomicAdd(&d_cursor[edge_dst(ei, e)], 1);
    d_esrc[slot] = edge_src(ei, e);
}

// ---------------- stage 2: HMMA GEMM (2-stage cp.async, 2 CTA/SM) ------------
__device__ __forceinline__ void load_stage(uint32_t st, int m0, int n0, int k0,
                                           const __nv_bfloat16* __restrict__ Bh,
                                           const __nv_bfloat16* __restrict__ Bl,
                                           int tid) {
#pragma unroll
    for (int i = tid; i < 512; i += 256) {
        int row = i >> 2, c = i & 3;
        uint32_t off = row * A_STRIDE + c * 16;
        size_t g = (size_t)(m0 + row) * FF + k0 + c * 8;
        cpa16(st + OFF_AHI + off, d_Ah + g);
        cpa16(st + OFF_ALO + off, d_Al + g);
    }
#pragma unroll
    for (int i = tid; i < 512; i += 256) {
        int row = i >> 4, c = i & 15;
        uint32_t off = row * B_STRIDE + c * 16;
        size_t g = (size_t)(k0 + row) * HF + n0 + c * 8;
        cpa16(st + OFF_BHI + off, Bh + g);
        cpa16(st + OFF_BLO + off, Bl + g);
    }
}

__global__ void __launch_bounds__(256, 2)
mmagemm_kernel(const float* __restrict__ biasL, const float* __restrict__ biasR) {
    extern __shared__ __align__(1024) char smem[];
    uint32_t sbase = smem_to_u32(smem);
    int tid = threadIdx.x;
    int wid = tid >> 5, lane = tid & 31;

    int bid = blockIdx.x;
    int gemm = (bid >= TILES_PER_GEMM) ? 1 : 0;
    int r = bid - gemm * TILES_PER_GEMM;
    int n0 = (r >> 2) * BN;
    int m0 = (r & 3) * BM;

    const __nv_bfloat16* Bh = gemm ? d_Brh : d_Blh;
    const __nv_bfloat16* Bl = gemm ? d_Brl : d_Bll;
    float* C = gemm ? d_xr : d_xl;
    const float* bias = gemm ? biasR : biasL;

    int wm = (wid & 1) * 64;
    int wn = (wid >> 1) * 32;

    uint32_t stg[2] = { sbase, sbase + STAGE_BYTES };

    float acc[4][4][4];
#pragma unroll
    for (int mf = 0; mf < 4; mf++)
#pragma unroll
        for (int nf = 0; nf < 4; nf++)
#pragma unroll
            for (int q = 0; q < 4; q++) acc[mf][nf][q] = 0.0f;

    load_stage(stg[0], m0, n0, 0, Bh, Bl, tid);
    CP_COMMIT();

    uint32_t a_lrow = (lane & 7) + ((lane >> 3) & 1) * 8;
    uint32_t a_kadd = (lane >> 4) * 16;
    uint32_t b_lrow = (lane & 7) + ((lane >> 3) & 1) * 8;
    uint32_t b_nadd = (lane >> 4) * 16;

    for (int kt = 0; kt < NK; kt++) {
        if (kt + 1 < NK) {
            load_stage(stg[(kt + 1) & 1], m0, n0, (kt + 1) * BK, Bh, Bl, tid);
            CP_COMMIT();
            CP_WAIT1();
        } else {
            CP_WAIT0();
        }
        __syncthreads();

        uint32_t st = stg[kt & 1];
#pragma unroll
        for (int kk = 0; kk < BK; kk += 16) {
            uint32_t ahi[4][4], alo[4][4], bhi[4][2], blo[4][2];
            uint32_t abase = st + (wm + a_lrow) * A_STRIDE + kk * 2 + a_kadd;
#pragma unroll
            for (int mf = 0; mf < 4; mf++) {
                uint32_t ad = abase + mf * 16 * A_STRIDE;
                LDSM_X4(ahi[mf][0], ahi[mf][1], ahi[mf][2], ahi[mf][3], ad + OFF_AHI);
            }
            uint32_t bbase = st + (kk + b_lrow) * B_STRIDE + wn * 2 + b_nadd;
            LDSM_X4T(bhi[0][0], bhi[0][1], bhi[1][0], bhi[1][1], bbase + OFF_BHI);
            LDSM_X4T(bhi[2][0], bhi[2][1], bhi[3][0], bhi[3][1], bbase + OFF_BHI + 32);
            LDSM_X4T(blo[0][0], blo[0][1], blo[1][0], blo[1][1], bbase + OFF_BLO);
            LDSM_X4T(blo[2][0], blo[2][1], blo[3][0], blo[3][1], bbase + OFF_BLO + 32);
#pragma unroll
            for (int mf = 0; mf < 4; mf++)
#pragma unroll
                for (int nf = 0; nf < 4; nf++) {
                    MMA16816(acc[mf][nf], ahi[mf], bhi[nf]);
                    MMA16816(acc[mf][nf], ahi[mf], blo[nf]);
                }
            // load A-lo after A-hi terms are issued (register lifetime split)
#pragma unroll
            for (int mf = 0; mf < 4; mf++) {
                uint32_t ad = abase + mf * 16 * A_STRIDE;
                LDSM_X4(alo[mf][0], alo[mf][1], alo[mf][2], alo[mf][3], ad + OFF_ALO);
            }
#pragma unroll
            for (int mf = 0; mf < 4; mf++)
#pragma unroll
                for (int nf = 0; nf < 4; nf++)
                    MMA16816(acc[mf][nf], alo[mf], bhi[nf]);
        }
        __syncthreads();
    }

    // epilogue
    int g = lane >> 2, tc = lane & 3;
#pragma unroll
    for (int mf = 0; mf < 4; mf++) {
#pragma unroll
        for (int nf = 0; nf < 4; nf++) {
            int row = m0 + wm + mf * 16 + g;
            int col = n0 + wn + nf * 8 + tc * 2;
            float b0 = bias[col], b1 = bias[col + 1];
            float2 v0 = make_float2(acc[mf][nf][0] + b0, acc[mf][nf][1] + b1);
            float2 v1 = make_float2(acc[mf][nf][2] + b0, acc[mf][nf][3] + b1);
            *(float2*)(C + (size_t)row * HF + col) = v0;
            *(float2*)(C + (size_t)(row + 8) * HF + col) = v1;
        }
    }
}

// ---------------- stage 3: fused logits + segment softmax (per dst) ----------
__global__ void __launch_bounds__(256)
logits_softmax_kernel(const float* __restrict__ att) {
    extern __shared__ float sm[];
    float* s_xr = sm;                 // HF floats
    float* s_lg = sm + HF;            // [HH][LS_CAP]
    int n = blockIdx.x, tid = threadIdx.x;
    int s0 = d_rowptr[n];
    int cnt = d_rowptr[n + 1] - s0;
    if (cnt > LS_CAP) cnt = LS_CAP;

    // cache xr[n]
    {
        const float4* xr = (const float4*)(d_xr + (size_t)n * HF);
        float4* sx = (float4*)s_xr;
        for (int i = tid; i < HF / 4; i += 256) sx[i] = xr[i];
    }
    __syncthreads();

    int wid = tid >> 5, lane = tid & 31;
    int h = wid & 3, ep = wid >> 2;       // 8 warps: head x edge-parity
    for (int si = ep; si < cnt; si += 2) {
        int src = d_esrc[s0 + si];
        const float4* pl = (const float4*)(d_xl + (size_t)src * HF + h * FF);
        const float4* pr = (const float4*)(s_xr + h * FF);
        const float4* pa = (const float4*)(att + h * FF);
        float s = 0.0f;
#pragma unroll 4
        for (int it = 0; it < 24; it++) {
            int idx = lane + it * 32;
            float4 a = pl[idx];
            float4 b = pr[idx];
            float4 w = pa[idx];
            float z;
            z = a.x + b.x; s += w.x * (z > 0.0f ? z : SLOPE * z);
            z = a.y + b.y; s += w.y * (z > 0.0f ? z : SLOPE * z);
            z = a.z + b.z; s += w.z * (z > 0.0f ? z : SLOPE * z);
            z = a.w + b.w; s += w.w * (z > 0.0f ? z : SLOPE * z);
        }
#pragma unroll
        for (int o = 16; o; o >>= 1) s += __shfl_xor_sync(0xFFFFFFFFu, s, o);
        if (lane == 0) s_lg[h * LS_CAP + si] = s;
    }
    __syncthreads();

    // softmax per head (warps 0..3)
    if (wid < 4) {
        float* lg = s_lg + wid * LS_CAP;
        float mx = -INFINITY;
        for (int si = lane; si < cnt; si += 32) mx = fmaxf(mx, lg[si]);
#pragma unroll
        for (int o = 16; o; o >>= 1) mx = fmaxf(mx, __shfl_xor_sync(0xFFFFFFFFu, mx, o));
        float den = 0.0f;
        for (int si = lane; si < cnt; si += 32) {
            float ex = expf(lg[si] - mx);
            lg[si] = ex;
            den += ex;
        }
#pragma unroll
        for (int o = 16; o; o >>= 1) den += __shfl_xor_sync(0xFFFFFFFFu, den, o);
        float inv = 1.0f / den;
        for (int si = lane; si < cnt; si += 32)
            d_alpha[(s0 + si) * HH + wid] = lg[si] * inv;
    }
}

// ---------------- stage 5: aggregation (alpha already normalized) ------------
__global__ void __launch_bounds__(256)
agg_kernel() {
    __shared__ int   s_src[128];
    __shared__ float s_al[HH][128];
    int n = blockIdx.x, tid = threadIdx.x;
    int s0 = d_rowptr[n], s1 = d_rowptr[n + 1];

    float4 acc[12];
#pragma unroll
    for (int j = 0; j < 12; j++) acc[j] = make_float4(0.f, 0.f, 0.f, 0.f);

    for (int base = s0; base < s1; base += 128) {
        int cnt = min(128, s1 - base);
        __syncthreads();
        if (tid < cnt) {
            s_src[tid] = d_esrc[base + tid];
            float4 a = *(const float4*)(d_alpha + (size_t)(base + tid) * HH);
            s_al[0][tid] = a.x; s_al[1][tid] = a.y;
            s_al[2][tid] = a.z; s_al[3][tid] = a.w;
        }
        __syncthreads();
        for (int s = 0; s < cnt; s++) {
            const float4* row = (const float4*)(d_xl + (size_t)s_src[s] * HF);
            float al0 = s_al[0][s], al1 = s_al[1][s], al2 = s_al[2][s], al3 = s_al[3][s];
#pragma unroll
            for (int j = 0; j < 12; j++) {
                float al = (j < 3) ? al0 : (j < 6) ? al1 : (j < 9) ? al2 : al3;
                float4 v = row[j * 256 + tid];
                acc[j].x += al * v.x;
                acc[j].y += al * v.y;
                acc[j].z += al * v.z;
                acc[j].w += al * v.w;
            }
        }
    }

#pragma unroll
    for (int j = 0; j < 12; j++)
        *(float4*)(d_agg + (size_t)n * HF + (j * 256 + tid) * 4) = acc[j];
}

// ---------------- stage 6: fc2+BN2+residual + FFN (fused) --------------------
__global__ void final_kernel(const float* __restrict__ x,
                             const float* __restrict__ gat_b,
                             const float* __restrict__ fc2W, const float* __restrict__ fc2b,
                             const float* __restrict__ b2g, const float* __restrict__ b2b,
                             const float* __restrict__ b2m, const float* __restrict__ b2v,
                             const float* __restrict__ f1W, const float* __restrict__ f1b,
                             const float* __restrict__ bf1g, const float* __restrict__ bf1b,
                             const float* __restrict__ bf1m, const float* __restrict__ bf1v,
                             const float* __restrict__ f2W, const float* __restrict__ f2b,
                             const float* __restrict__ bf2g, const float* __restrict__ bf2b,
                             const float* __restrict__ bf2m, const float* __restrict__ bf2v,
                             float* __restrict__ out) {
    int n = blockIdx.x;
    int p = blockIdx.y * 256 + threadIdx.x;

    float ch[HH * CC];
#pragma unroll
    for (int h = 0; h < HH; h++)
#pragma unroll
        for (int c = 0; c < CC; c++)
            ch[h * CC + c] = d_agg[(size_t)n * HF + h * FF + c * PIX + p]
                           + gat_b[h * FF + c * PIX + p];

    float gv[CC];
#pragma unroll
    for (int oc = 0; oc < CC; oc++) {
        float t = fc2b[oc];
#pragma unroll
        for (int k = 0; k < HH * CC; k++) t += fc2W[oc * (HH * CC) + k] * ch[k];
        float inv = b2g[oc] * rsqrtf(b2v[oc] + BEPS);
        gv[oc] = t * inv + b2b[oc] - b2m[oc] * inv + x[(size_t)n * FF + oc * PIX + p];
    }
    float f1[CC];
#pragma unroll
    for (int oc = 0; oc < CC; oc++) {
        float t = f1b[oc];
#pragma unroll
        for (int ic = 0; ic < CC; ic++) t += f1W[oc * CC + ic] * gv[ic];
        float inv = bf1g[oc] * rsqrtf(bf1v[oc] + BEPS);
        float val = t * inv + bf1b[oc] - bf1m[oc] * inv;
        f1[oc] = val > 0.0f ? val : 0.0f;
    }
#pragma unroll
    for (int oc = 0; oc < CC; oc++) {
        float t = f2b[oc];
#pragma unroll
        for (int ic = 0; ic < CC; ic++) t += f2W[oc * CC + ic] * f1[ic];
        float inv = bf2g[oc] * rsqrtf(bf2v[oc] + BEPS);
        float val = t * inv + bf2b[oc] - bf2m[oc] * inv;
        out[(size_t)n * FF + oc * PIX + p] = val + gv[oc];
    }
}

// ---------------- launch -----------------------------------------------------
extern "C" void kernel_launch(void* const* d_in, const int* in_sizes, int n_in,
                              void* d_out, int out_size) {
    const float* x     = (const float*)d_in[0];
    const int*   ei    = (const int*)d_in[1];
    const float* fc1W  = (const float*)d_in[2];
    const float* fc1b  = (const float*)d_in[3];
    const float* b1g   = (const float*)d_in[4];
    const float* b1b   = (const float*)d_in[5];
    const float* b1m   = (const float*)d_in[6];
    const float* b1v   = (const float*)d_in[7];
    const float* Wl    = (const float*)d_in[8];
    const float* bl    = (const float*)d_in[9];
    const float* Wr    = (const float*)d_in[10];
    const float* br    = (const float*)d_in[11];
    const float* att   = (const float*)d_in[12];
    const float* gat_b = (const float*)d_in[13];
    const float* fc2W  = (const float*)d_in[14];
    const float* fc2b  = (const float*)d_in[15];
    const float* b2g   = (const float*)d_in[16];
    const float* b2b   = (const float*)d_in[17];
    const float* b2m   = (const float*)d_in[18];
    const float* b2v   = (const float*)d_in[19];
    const float* f1W   = (const float*)d_in[20];
    const float* f1b   = (const float*)d_in[21];
    const float* bf1g  = (const float*)d_in[22];
    const float* bf1b  = (const float*)d_in[23];
    const float* bf1m  = (const float*)d_in[24];
    const float* bf1v  = (const float*)d_in[25];
    const float* f2W   = (const float*)d_in[26];
    const float* f2b   = (const float*)d_in[27];
    const float* bf2g  = (const float*)d_in[28];
    const float* bf2b  = (const float*)d_in[29];
    const float* bf2m  = (const float*)d_in[30];
    const float* bf2v  = (const float*)d_in[31];
    float* out = (float*)d_out;

    cudaFuncSetAttribute(mmagemm_kernel, cudaFuncAttributeMaxDynamicSharedMemorySize, SMEM_TOTAL);
    cudaFuncSetAttribute(logits_softmax_kernel, cudaFuncAttributeMaxDynamicSharedMemorySize, LS_SMEM);

    wsplit_kernel<<<dim3((FF * HF) / (256 * 4), 2), 256>>>(Wl, Wr);
    fc1_bn_kernel<<<dim3(NN, 4), 256>>>(x, fc1W, fc1b, b1g, b1b, b1m, b1v);
    init_kernel<<<2, 256>>>();
    deg_kernel<<<(ET + 255) / 256, 256>>>(ei);
    scan_kernel<<<1, NN>>>();
    scatter_kernel<<<(ET + 255) / 256, 256>>>(ei);
    mmagemm_kernel<<<2 * TILES_PER_GEMM, 256, SMEM_TOTAL>>>(bl, br);
    logits_softmax_kernel<<<NN, 256, LS_SMEM>>>(att);
    agg_kernel<<<NN, 256>>>();
    final_kernel<<<dim3(NN, 4), 256>>>(x, gat_b, fc2W, fc2b, b2g, b2b, b2m, b2v,
                                       f1W, f1b, bf1g, bf1b, bf1m, bf1v,
                                       f2W, f2b, bf2g, bf2b, bf2m, bf2v, out);
}

// round 6
// speedup vs baseline: 1.4458x; 1.4325x over previous
#include <cuda_runtime.h>
#include <cuda_bf16.h>
#include <cuda_fp16.h>
#include <math.h>
#include <stdint.h>

#define NN 512
#define CC 3
#define PIX 1024
#define FF 3072          // K dim
#define HH 4
#define HF 12288         // N dim
#define EE 4096
#define ET 4608
#define BEPS 1e-5f
#define SLOPE 0.2f

// GEMM tiling
#define BM 128
#define BN 128
#define BK 32
#define NK (FF / BK)             // 96
#define TILES_PER_GEMM ((NN / BM) * (HF / BN))   // 384

// smem stage layout (fp16, padded rows for conflict-free ldmatrix)
#define A_STRIDE 80              // 32 halves = 64 B + 16 pad
#define B_STRIDE 272             // 128 halves = 256 B + 16 pad
#define OFF_AHI 0
#define OFF_ALO (BM * A_STRIDE)                  // 10240
#define OFF_BH  (2 * BM * A_STRIDE)              // 20480
#define STAGE_BYTES (OFF_BH + BK * B_STRIDE)     // 29184
#define NSTAGE 3
#define SMEM_TOTAL (NSTAGE * STAGE_BYTES)        // 87552

// logits kernel smem: xr cache + logits buffer
#define LS_CAP 128
#define LS_SMEM (HF * 4 + HH * LS_CAP * 4)       // 51200

// ---------------- scratch ----------------------------------------------------
__device__ __half d_Ah[NN * FF];
__device__ __half d_Al[NN * FF];
__device__ __half d_Bl16[(size_t)FF * HF];
__device__ __half d_Br16[(size_t)FF * HF];
__device__ float d_xl[(size_t)NN * HF];
__device__ float d_xr[(size_t)NN * HF];
__device__ float d_alpha[ET * HH];
__device__ float d_agg[(size_t)NN * HF];
__device__ int   d_rowptr[NN + 1];
__device__ int   d_esrc[ET];

// ---------------- PTX helpers ------------------------------------------------
__device__ __forceinline__ uint32_t smem_to_u32(const void* p) {
    uint32_t a;
    asm("{ .reg .u64 t; cvta.to.shared.u64 t, %1; cvt.u32.u64 %0, t; }" : "=r"(a) : "l"(p));
    return a;
}
__device__ __forceinline__ void cpa16(uint32_t dst, const void* src) {
    asm volatile("cp.async.cg.shared.global [%0], [%1], 16;" :: "r"(dst), "l"(src));
}
#define CP_COMMIT() asm volatile("cp.async.commit_group;" ::: "memory")
#define CP_WAIT0()  asm volatile("cp.async.wait_group 0;" ::: "memory")
#define CP_WAIT1()  asm volatile("cp.async.wait_group 1;" ::: "memory")

#define LDSM_X4(r0, r1, r2, r3, addr) \
    asm volatile("ldmatrix.sync.aligned.m8n8.x4.shared.b16 {%0,%1,%2,%3}, [%4];" \
        : "=r"(r0), "=r"(r1), "=r"(r2), "=r"(r3) : "r"(addr))
#define LDSM_X4T(r0, r1, r2, r3, addr) \
    asm volatile("ldmatrix.sync.aligned.m8n8.x4.trans.shared.b16 {%0,%1,%2,%3}, [%4];" \
        : "=r"(r0), "=r"(r1), "=r"(r2), "=r"(r3) : "r"(addr))

#define MMA16816F16(d, a, b) \
    asm volatile("mma.sync.aligned.m16n8k16.row.col.f32.f16.f16.f32 " \
        "{%0,%1,%2,%3}, {%4,%5,%6,%7}, {%8,%9}, {%0,%1,%2,%3};" \
        : "+f"((d)[0]), "+f"((d)[1]), "+f"((d)[2]), "+f"((d)[3]) \
        : "r"((a)[0]), "r"((a)[1]), "r"((a)[2]), "r"((a)[3]), "r"((b)[0]), "r"((b)[1]))

// ---------------- misc -------------------------------------------------------
__device__ __forceinline__ int edge_src(const int* ei, int e) { return (e < EE) ? ei[e] : (e - EE); }
__device__ __forceinline__ int edge_dst(const int* ei, int e) { return (e < EE) ? ei[EE + e] : (e - EE); }

// ---------------- stage 1: fc1 + BN1 -> fp16 hi/lo ---------------------------
__global__ void fc1_bn_kernel(const float* __restrict__ x,
                              const float* __restrict__ W,
                              const float* __restrict__ b,
                              const float* __restrict__ bg,
                              const float* __restrict__ bb,
                              const float* __restrict__ bm,
                              const float* __restrict__ bv) {
    int n = blockIdx.x;
    int p = blockIdx.y * 256 + threadIdx.x;
    float xin[CC];
#pragma unroll
    for (int c = 0; c < CC; c++) xin[c] = x[(size_t)n * FF + c * PIX + p];
#pragma unroll
    for (int oc = 0; oc < CC; oc++) {
        float t = b[oc];
#pragma unroll
        for (int ic = 0; ic < CC; ic++) t += W[oc * CC + ic] * xin[ic];
        float inv = bg[oc] * rsqrtf(bv[oc] + BEPS);
        float hv = t * inv + bb[oc] - bm[oc] * inv;
        __half hi = __float2half_rn(hv);
        size_t o = (size_t)n * FF + oc * PIX + p;
        d_Ah[o] = hi;
        d_Al[o] = __float2half_rn(hv - __half2float(hi));
    }
}

// ---------------- weight fp32 -> fp16 convert (streaming) --------------------
__global__ void wconv_kernel(const float* __restrict__ Wl, const float* __restrict__ Wr) {
    const float* W = blockIdx.y ? Wr : Wl;
    __half* B = blockIdx.y ? d_Br16 : d_Bl16;
    size_t i = ((size_t)blockIdx.x * 256 + threadIdx.x) * 8;
    float4 v0 = *(const float4*)(W + i);
    float4 v1 = *(const float4*)(W + i + 4);
    __half2 h[4];
    h[0] = __floats2half2_rn(v0.x, v0.y);
    h[1] = __floats2half2_rn(v0.z, v0.w);
    h[2] = __floats2half2_rn(v1.x, v1.y);
    h[3] = __floats2half2_rn(v1.z, v1.w);
    *(uint4*)(B + i) = *(uint4*)h;
}

// ---------------- CSR build: init + deg + scan + scatter, one CTA ------------
__global__ void __launch_bounds__(512)
csr_kernel(const int* __restrict__ ei) {
    __shared__ int sdeg[NN];
    __shared__ int sscan[NN];
    __shared__ int scur[NN];
    int t = threadIdx.x;
    sdeg[t] = 0;
    __syncthreads();
    for (int e = t; e < ET; e += NN) atomicAdd(&sdeg[edge_dst(ei, e)], 1);
    __syncthreads();
    sscan[t] = sdeg[t];
    __syncthreads();
    for (int o = 1; o < NN; o <<= 1) {
        int v = (t >= o) ? sscan[t - o] : 0;
        __syncthreads();
        sscan[t] += v;
        __syncthreads();
    }
    if (t == 0) d_rowptr[0] = 0;
    d_rowptr[t + 1] = sscan[t];
    scur[t] = sscan[t] - sdeg[t];
    __syncthreads();
    for (int e = t; e < ET; e += NN) {
        int slot = atomicAdd(&scur[edge_dst(ei, e)], 1);
        d_esrc[slot] = edge_src(ei, e);
    }
}

// ---------------- stage 2: HMMA GEMM (fp16 2-pass, 3-stage cp.async) ---------
__device__ __forceinline__ void load_stage(uint32_t st, int m0, int n0, int k0,
                                           const __half* __restrict__ B, int tid) {
#pragma unroll
    for (int i = tid; i < 512; i += 256) {
        int row = i >> 2, c = i & 3;
        uint32_t off = row * A_STRIDE + c * 16;
        size_t g = (size_t)(m0 + row) * FF + k0 + c * 8;
        cpa16(st + OFF_AHI + off, d_Ah + g);
        cpa16(st + OFF_ALO + off, d_Al + g);
    }
#pragma unroll
    for (int i = tid; i < 512; i += 256) {
        int row = i >> 4, c = i & 15;
        uint32_t off = row * B_STRIDE + c * 16;
        size_t g = (size_t)(k0 + row) * HF + n0 + c * 8;
        cpa16(st + OFF_BH + off, B + g);
    }
}

__global__ void __launch_bounds__(256)
mmagemm_kernel(const float* __restrict__ biasL, const float* __restrict__ biasR) {
    extern __shared__ __align__(1024) char smem[];
    uint32_t sbase = smem_to_u32(smem);
    int tid = threadIdx.x;
    int wid = tid >> 5, lane = tid & 31;

    int bid = blockIdx.x;
    int gemm = (bid >= TILES_PER_GEMM) ? 1 : 0;
    int r = bid - gemm * TILES_PER_GEMM;
    int n0 = (r >> 2) * BN;
    int m0 = (r & 3) * BM;

    const __half* B = gemm ? d_Br16 : d_Bl16;
    float* C = gemm ? d_xr : d_xl;
    const float* bias = gemm ? biasR : biasL;

    int wm = (wid & 1) * 64;
    int wn = (wid >> 1) * 32;

    uint32_t stg[NSTAGE];
#pragma unroll
    for (int s = 0; s < NSTAGE; s++) stg[s] = sbase + s * STAGE_BYTES;

    float acc[4][4][4];
#pragma unroll
    for (int mf = 0; mf < 4; mf++)
#pragma unroll
        for (int nf = 0; nf < 4; nf++)
#pragma unroll
            for (int q = 0; q < 4; q++) acc[mf][nf][q] = 0.0f;

    load_stage(stg[0], m0, n0, 0, B, tid);
    CP_COMMIT();
    load_stage(stg[1], m0, n0, BK, B, tid);
    CP_COMMIT();

    uint32_t a_lrow = (lane & 7) + ((lane >> 3) & 1) * 8;
    uint32_t a_kadd = (lane >> 4) * 16;
    uint32_t b_lrow = (lane & 7) + ((lane >> 3) & 1) * 8;
    uint32_t b_nadd = (lane >> 4) * 16;

    for (int kt = 0; kt < NK; kt++) {
        if (kt + 2 < NK) { CP_WAIT1(); } else { CP_WAIT0(); }
        __syncthreads();
        if (kt + 2 < NK) {
            load_stage(stg[(kt + 2) % NSTAGE], m0, n0, (kt + 2) * BK, B, tid);
            CP_COMMIT();
        }
        uint32_t st = stg[kt % NSTAGE];
#pragma unroll
        for (int kk = 0; kk < BK; kk += 16) {
            uint32_t ahi[4][4], alo[4][4], bh[4][2];
            uint32_t abase = st + (wm + a_lrow) * A_STRIDE + kk * 2 + a_kadd;
#pragma unroll
            for (int mf = 0; mf < 4; mf++) {
                uint32_t ad = abase + mf * 16 * A_STRIDE;
                LDSM_X4(ahi[mf][0], ahi[mf][1], ahi[mf][2], ahi[mf][3], ad + OFF_AHI);
                LDSM_X4(alo[mf][0], alo[mf][1], alo[mf][2], alo[mf][3], ad + OFF_ALO);
            }
            uint32_t bbase = st + (kk + b_lrow) * B_STRIDE + wn * 2 + b_nadd;
            LDSM_X4T(bh[0][0], bh[0][1], bh[1][0], bh[1][1], bbase + OFF_BH);
            LDSM_X4T(bh[2][0], bh[2][1], bh[3][0], bh[3][1], bbase + OFF_BH + 32);
#pragma unroll
            for (int mf = 0; mf < 4; mf++)
#pragma unroll
                for (int nf = 0; nf < 4; nf++) {
                    MMA16816F16(acc[mf][nf], ahi[mf], bh[nf]);
                    MMA16816F16(acc[mf][nf], alo[mf], bh[nf]);
                }
        }
    }

    // epilogue
    int g = lane >> 2, tc = lane & 3;
#pragma unroll
    for (int mf = 0; mf < 4; mf++) {
#pragma unroll
        for (int nf = 0; nf < 4; nf++) {
            int row = m0 + wm + mf * 16 + g;
            int col = n0 + wn + nf * 8 + tc * 2;
            float b0 = bias[col], b1 = bias[col + 1];
            float2 v0 = make_float2(acc[mf][nf][0] + b0, acc[mf][nf][1] + b1);
            float2 v1 = make_float2(acc[mf][nf][2] + b0, acc[mf][nf][3] + b1);
            *(float2*)(C + (size_t)row * HF + col) = v0;
            *(float2*)(C + (size_t)(row + 8) * HF + col) = v1;
        }
    }
}

// ---------------- stage 3: fused logits + segment softmax (per dst) ----------
__global__ void __launch_bounds__(256)
logits_softmax_kernel(const float* __restrict__ att) {
    extern __shared__ float sm[];
    float* s_xr = sm;                 // HF floats
    float* s_lg = sm + HF;            // [HH][LS_CAP]
    int n = blockIdx.x, tid = threadIdx.x;
    int s0 = d_rowptr[n];
    int cnt = d_rowptr[n + 1] - s0;
    if (cnt > LS_CAP) cnt = LS_CAP;

    {
        const float4* xr = (const float4*)(d_xr + (size_t)n * HF);
        float4* sx = (float4*)s_xr;
        for (int i = tid; i < HF / 4; i += 256) sx[i] = xr[i];
    }
    __syncthreads();

    int wid = tid >> 5, lane = tid & 31;
    int h = wid & 3, ep = wid >> 2;
    for (int si = ep; si < cnt; si += 2) {
        int src = d_esrc[s0 + si];
        const float4* pl = (const float4*)(d_xl + (size_t)src * HF + h * FF);
        const float4* pr = (const float4*)(s_xr + h * FF);
        const float4* pa = (const float4*)(att + h * FF);
        float s = 0.0f;
#pragma unroll 4
        for (int it = 0; it < 24; it++) {
            int idx = lane + it * 32;
            float4 a = pl[idx];
            float4 b = pr[idx];
            float4 w = pa[idx];
            float z;
            z = a.x + b.x; s += w.x * (z > 0.0f ? z : SLOPE * z);
            z = a.y + b.y; s += w.y * (z > 0.0f ? z : SLOPE * z);
            z = a.z + b.z; s += w.z * (z > 0.0f ? z : SLOPE * z);
            z = a.w + b.w; s += w.w * (z > 0.0f ? z : SLOPE * z);
        }
#pragma unroll
        for (int o = 16; o; o >>= 1) s += __shfl_xor_sync(0xFFFFFFFFu, s, o);
        if (lane == 0) s_lg[h * LS_CAP + si] = s;
    }
    __syncthreads();

    if (wid < 4) {
        float* lg = s_lg + wid * LS_CAP;
        float mx = -INFINITY;
        for (int si = lane; si < cnt; si += 32) mx = fmaxf(mx, lg[si]);
#pragma unroll
        for (int o = 16; o; o >>= 1) mx = fmaxf(mx, __shfl_xor_sync(0xFFFFFFFFu, mx, o));
        float den = 0.0f;
        for (int si = lane; si < cnt; si += 32) {
            float ex = expf(lg[si] - mx);
            lg[si] = ex;
            den += ex;
        }
#pragma unroll
        for (int o = 16; o; o >>= 1) den += __shfl_xor_sync(0xFFFFFFFFu, den, o);
        float inv = 1.0f / den;
        for (int si = lane; si < cnt; si += 32)
            d_alpha[(s0 + si) * HH + wid] = lg[si] * inv;
    }
}

// ---------------- stage 5: aggregation ---------------------------------------
__global__ void __launch_bounds__(256)
agg_kernel() {
    __shared__ int   s_src[128];
    __shared__ float s_al[HH][128];
    int n = blockIdx.x, tid = threadIdx.x;
    int s0 = d_rowptr[n], s1 = d_rowptr[n + 1];

    float4 acc[12];
#pragma unroll
    for (int j = 0; j < 12; j++) acc[j] = make_float4(0.f, 0.f, 0.f, 0.f);

    for (int base = s0; base < s1; base += 128) {
        int cnt = min(128, s1 - base);
        __syncthreads();
        if (tid < cnt) {
            s_src[tid] = d_esrc[base + tid];
            float4 a = *(const float4*)(d_alpha + (size_t)(base + tid) * HH);
            s_al[0][tid] = a.x; s_al[1][tid] = a.y;
            s_al[2][tid] = a.z; s_al[3][tid] = a.w;
        }
        __syncthreads();
        for (int s = 0; s < cnt; s++) {
            const float4* row = (const float4*)(d_xl + (size_t)s_src[s] * HF);
            float al0 = s_al[0][s], al1 = s_al[1][s], al2 = s_al[2][s], al3 = s_al[3][s];
#pragma unroll
            for (int j = 0; j < 12; j++) {
                float al = (j < 3) ? al0 : (j < 6) ? al1 : (j < 9) ? al2 : al3;
                float4 v = row[j * 256 + tid];
                acc[j].x += al * v.x;
                acc[j].y += al * v.y;
                acc[j].z += al * v.z;
                acc[j].w += al * v.w;
            }
        }
    }

#pragma unroll
    for (int j = 0; j < 12; j++)
        *(float4*)(d_agg + (size_t)n * HF + (j * 256 + tid) * 4) = acc[j];
}

// ---------------- stage 6: fc2+BN2+residual + FFN (fused) --------------------
__global__ void final_kernel(const float* __restrict__ x,
                             const float* __restrict__ gat_b,
                             const float* __restrict__ fc2W, const float* __restrict__ fc2b,
                             const float* __restrict__ b2g, const float* __restrict__ b2b,
                             const float* __restrict__ b2m, const float* __restrict__ b2v,
                             const float* __restrict__ f1W, const float* __restrict__ f1b,
                             const float* __restrict__ bf1g, const float* __restrict__ bf1b,
                             const float* __restrict__ bf1m, const float* __restrict__ bf1v,
                             const float* __restrict__ f2W, const float* __restrict__ f2b,
                             const float* __restrict__ bf2g, const float* __restrict__ bf2b,
                             const float* __restrict__ bf2m, const float* __restrict__ bf2v,
                             float* __restrict__ out) {
    int n = blockIdx.x;
    int p = blockIdx.y * 256 + threadIdx.x;

    float ch[HH * CC];
#pragma unroll
    for (int h = 0; h < HH; h++)
#pragma unroll
        for (int c = 0; c < CC; c++)
            ch[h * CC + c] = d_agg[(size_t)n * HF + h * FF + c * PIX + p]
                           + gat_b[h * FF + c * PIX + p];

    float gv[CC];
#pragma unroll
    for (int oc = 0; oc < CC; oc++) {
        float t = fc2b[oc];
#pragma unroll
        for (int k = 0; k < HH * CC; k++) t += fc2W[oc * (HH * CC) + k] * ch[k];
        float inv = b2g[oc] * rsqrtf(b2v[oc] + BEPS);
        gv[oc] = t * inv + b2b[oc] - b2m[oc] * inv + x[(size_t)n * FF + oc * PIX + p];
    }
    float f1[CC];
#pragma unroll
    for (int oc = 0; oc < CC; oc++) {
        float t = f1b[oc];
#pragma unroll
        for (int ic = 0; ic < CC; ic++) t += f1W[oc * CC + ic] * gv[ic];
        float inv = bf1g[oc] * rsqrtf(bf1v[oc] + BEPS);
        float val = t * inv + bf1b[oc] - bf1m[oc] * inv;
        f1[oc] = val > 0.0f ? val : 0.0f;
    }
#pragma unroll
    for (int oc = 0; oc < CC; oc++) {
        float t = f2b[oc];
#pragma unroll
        for (int ic = 0; ic < CC; ic++) t += f2W[oc * CC + ic] * f1[ic];
        float inv = bf2g[oc] * rsqrtf(bf2v[oc] + BEPS);
        float val = t * inv + bf2b[oc] - bf2m[oc] * inv;
        out[(size_t)n * FF + oc * PIX + p] = val + gv[oc];
    }
}

// ---------------- launch -----------------------------------------------------
extern "C" void kernel_launch(void* const* d_in, const int* in_sizes, int n_in,
                              void* d_out, int out_size) {
    const float* x     = (const float*)d_in[0];
    const int*   ei    = (const int*)d_in[1];
    const float* fc1W  = (const float*)d_in[2];
    const float* fc1b  = (const float*)d_in[3];
    const float* b1g   = (const float*)d_in[4];
    const float* b1b   = (const float*)d_in[5];
    const float* b1m   = (const float*)d_in[6];
    const float* b1v   = (const float*)d_in[7];
    const float* Wl    = (const float*)d_in[8];
    const float* bl    = (const float*)d_in[9];
    const float* Wr    = (const float*)d_in[10];
    const float* br    = (const float*)d_in[11];
    const float* att   = (const float*)d_in[12];
    const float* gat_b = (const float*)d_in[13];
    const float* fc2W  = (const float*)d_in[14];
    const float* fc2b  = (const float*)d_in[15];
    const float* b2g   = (const float*)d_in[16];
    const float* b2b   = (const float*)d_in[17];
    const float* b2m   = (const float*)d_in[18];
    const float* b2v   = (const float*)d_in[19];
    const float* f1W   = (const float*)d_in[20];
    const float* f1b   = (const float*)d_in[21];
    const float* bf1g  = (const float*)d_in[22];
    const float* bf1b  = (const float*)d_in[23];
    const float* bf1m  = (const float*)d_in[24];
    const float* bf1v  = (const float*)d_in[25];
    const float* f2W   = (const float*)d_in[26];
    const float* f2b   = (const float*)d_in[27];
    const float* bf2g  = (const float*)d_in[28];
    const float* bf2b  = (const float*)d_in[29];
    const float* bf2m  = (const float*)d_in[30];
    const float* bf2v  = (const float*)d_in[31];
    float* out = (float*)d_out;

    cudaFuncSetAttribute(mmagemm_kernel, cudaFuncAttributeMaxDynamicSharedMemorySize, SMEM_TOTAL);
    cudaFuncSetAttribute(logits_softmax_kernel, cudaFuncAttributeMaxDynamicSharedMemorySize, LS_SMEM);

    wconv_kernel<<<dim3((FF * HF) / (256 * 8), 2), 256>>>(Wl, Wr);
    fc1_bn_kernel<<<dim3(NN, 4), 256>>>(x, fc1W, fc1b, b1g, b1b, b1m, b1v);
    csr_kernel<<<1, NN>>>(ei);
    mmagemm_kernel<<<2 * TILES_PER_GEMM, 256, SMEM_TOTAL>>>(bl, br);
    logits_softmax_kernel<<<NN, 256, LS_SMEM>>>(att);
    agg_kernel<<<NN, 256>>>();
    final_kernel<<<dim3(NN, 4), 256>>>(x, gat_b, fc2W, fc2b, b2g, b2b, b2m, b2v,
                                       f1W, f1b, bf1g, bf1b, bf1m, bf1v,
                                       f2W, f2b, bf2g, bf2b, bf2m, bf2v, out);
}

// round 7
// speedup vs baseline: 1.5002x; 1.0376x over previous
#include <cuda_runtime.h>
#include <cuda_bf16.h>
#include <cuda_fp16.h>
#include <math.h>
#include <stdint.h>

#define NN 512
#define CC 3
#define PIX 1024
#define FF 3072          // K dim
#define HH 4
#define HF 12288         // N dim
#define EE 4096
#define ET 4608
#define BEPS 1e-5f
#define SLOPE 0.2f

// GEMM tiling
#define BM 128
#define BN 128
#define BK 32
#define NK (FF / BK)             // 96
#define TILES_PER_GEMM ((NN / BM) * (HF / BN))   // 384

// smem stage layout (fp16, padded rows for conflict-free ldmatrix)
#define A_STRIDE 80              // 32 halves = 64 B + 16 pad
#define B_STRIDE 272             // 128 halves = 256 B + 16 pad
#define OFF_AHI 0
#define OFF_ALO (BM * A_STRIDE)                  // 10240
#define OFF_BH  (2 * BM * A_STRIDE)              // 20480
#define STAGE_BYTES (OFF_BH + BK * B_STRIDE)     // 29184
#define NSTAGE 3
#define SMEM_TOTAL (NSTAGE * STAGE_BYTES)        // 87552

// logits kernel smem: xr cache + logits buffer
#define LS_CAP 128
#define LS_SMEM (HF * 4 + HH * LS_CAP * 4)       // 51200

// ---------------- scratch ----------------------------------------------------
__device__ __half d_Ah[NN * FF];
__device__ __half d_Al[NN * FF];
__device__ __half d_Bl16[(size_t)FF * HF];
__device__ __half d_Br16[(size_t)FF * HF];
__device__ float d_xl[(size_t)NN * HF];
__device__ float d_xr[(size_t)NN * HF];
__device__ float d_alpha[ET * HH];
__device__ float d_agg[(size_t)NN * HF];
__device__ int   d_rowptr[NN + 1];
__device__ int   d_esrc[ET];

// ---------------- PTX helpers ------------------------------------------------
__device__ __forceinline__ uint32_t smem_to_u32(const void* p) {
    uint32_t a;
    asm("{ .reg .u64 t; cvta.to.shared.u64 t, %1; cvt.u32.u64 %0, t; }" : "=r"(a) : "l"(p));
    return a;
}
__device__ __forceinline__ void cpa16(uint32_t dst, const void* src) {
    asm volatile("cp.async.cg.shared.global [%0], [%1], 16;" :: "r"(dst), "l"(src));
}
#define CP_COMMIT() asm volatile("cp.async.commit_group;" ::: "memory")
#define CP_WAIT0()  asm volatile("cp.async.wait_group 0;" ::: "memory")
#define CP_WAIT1()  asm volatile("cp.async.wait_group 1;" ::: "memory")

#define LDSM_X4(r0, r1, r2, r3, addr) \
    asm volatile("ldmatrix.sync.aligned.m8n8.x4.shared.b16 {%0,%1,%2,%3}, [%4];" \
        : "=r"(r0), "=r"(r1), "=r"(r2), "=r"(r3) : "r"(addr))
#define LDSM_X4T(r0, r1, r2, r3, addr) \
    asm volatile("ldmatrix.sync.aligned.m8n8.x4.trans.shared.b16 {%0,%1,%2,%3}, [%4];" \
        : "=r"(r0), "=r"(r1), "=r"(r2), "=r"(r3) : "r"(addr))

#define MMA16816F16(d, a, b) \
    asm volatile("mma.sync.aligned.m16n8k16.row.col.f32.f16.f16.f32 " \
        "{%0,%1,%2,%3}, {%4,%5,%6,%7}, {%8,%9}, {%0,%1,%2,%3};" \
        : "+f"((d)[0]), "+f"((d)[1]), "+f"((d)[2]), "+f"((d)[3]) \
        : "r"((a)[0]), "r"((a)[1]), "r"((a)[2]), "r"((a)[3]), "r"((b)[0]), "r"((b)[1]))

// ---------------- misc -------------------------------------------------------
__device__ __forceinline__ int edge_src(const int* ei, int e) { return (e < EE) ? ei[e] : (e - EE); }
__device__ __forceinline__ int edge_dst(const int* ei, int e) { return (e < EE) ? ei[EE + e] : (e - EE); }

// ---------------- stage 1: fc1 + BN1 -> fp16 hi/lo ---------------------------
__global__ void fc1_bn_kernel(const float* __restrict__ x,
                              const float* __restrict__ W,
                              const float* __restrict__ b,
                              const float* __restrict__ bg,
                              const float* __restrict__ bb,
                              const float* __restrict__ bm,
                              const float* __restrict__ bv) {
    int n = blockIdx.x;
    int p = blockIdx.y * 256 + threadIdx.x;
    float xin[CC];
#pragma unroll
    for (int c = 0; c < CC; c++) xin[c] = x[(size_t)n * FF + c * PIX + p];
#pragma unroll
    for (int oc = 0; oc < CC; oc++) {
        float t = b[oc];
#pragma unroll
        for (int ic = 0; ic < CC; ic++) t += W[oc * CC + ic] * xin[ic];
        float inv = bg[oc] * rsqrtf(bv[oc] + BEPS);
        float hv = t * inv + bb[oc] - bm[oc] * inv;
        __half hi = __float2half_rn(hv);
        size_t o = (size_t)n * FF + oc * PIX + p;
        d_Ah[o] = hi;
        d_Al[o] = __float2half_rn(hv - __half2float(hi));
    }
}

// ---------------- weight fp32 -> fp16 convert (streaming) --------------------
__global__ void wconv_kernel(const float* __restrict__ Wl, const float* __restrict__ Wr) {
    const float* W = blockIdx.y ? Wr : Wl;
    __half* B = blockIdx.y ? d_Br16 : d_Bl16;
    size_t i = ((size_t)blockIdx.x * 256 + threadIdx.x) * 8;
    float4 v0 = *(const float4*)(W + i);
    float4 v1 = *(const float4*)(W + i + 4);
    __half2 h[4];
    h[0] = __floats2half2_rn(v0.x, v0.y);
    h[1] = __floats2half2_rn(v0.z, v0.w);
    h[2] = __floats2half2_rn(v1.x, v1.y);
    h[3] = __floats2half2_rn(v1.z, v1.w);
    *(uint4*)(B + i) = *(uint4*)h;
}

// ---------------- CSR build: init + deg + scan + scatter, one CTA ------------
__global__ void __launch_bounds__(512)
csr_kernel(const int* __restrict__ ei) {
    __shared__ int sdeg[NN];
    __shared__ int sscan[NN];
    __shared__ int scur[NN];
    int t = threadIdx.x;
    sdeg[t] = 0;
    __syncthreads();
    for (int e = t; e < ET; e += NN) atomicAdd(&sdeg[edge_dst(ei, e)], 1);
    __syncthreads();
    sscan[t] = sdeg[t];
    __syncthreads();
    for (int o = 1; o < NN; o <<= 1) {
        int v = (t >= o) ? sscan[t - o] : 0;
        __syncthreads();
        sscan[t] += v;
        __syncthreads();
    }
    if (t == 0) d_rowptr[0] = 0;
    d_rowptr[t + 1] = sscan[t];
    scur[t] = sscan[t] - sdeg[t];
    __syncthreads();
    for (int e = t; e < ET; e += NN) {
        int slot = atomicAdd(&scur[edge_dst(ei, e)], 1);
        d_esrc[slot] = edge_src(ei, e);
    }
}

// ---------------- stage 2: HMMA GEMM (fp16 2-pass, warp tile 32x64) ----------
__device__ __forceinline__ void load_stage(uint32_t st, int m0, int n0, int k0,
                                           const __half* __restrict__ B, int tid) {
#pragma unroll
    for (int i = tid; i < 512; i += 256) {
        int row = i >> 2, c = i & 3;
        uint32_t off = row * A_STRIDE + c * 16;
        size_t g = (size_t)(m0 + row) * FF + k0 + c * 8;
        cpa16(st + OFF_AHI + off, d_Ah + g);
        cpa16(st + OFF_ALO + off, d_Al + g);
    }
#pragma unroll
    for (int i = tid; i < 512; i += 256) {
        int row = i >> 4, c = i & 15;
        uint32_t off = row * B_STRIDE + c * 16;
        size_t g = (size_t)(k0 + row) * HF + n0 + c * 8;
        cpa16(st + OFF_BH + off, B + g);
    }
}

__global__ void __launch_bounds__(256)
mmagemm_kernel(const float* __restrict__ biasL, const float* __restrict__ biasR) {
    extern __shared__ __align__(1024) char smem[];
    uint32_t sbase = smem_to_u32(smem);
    int tid = threadIdx.x;
    int wid = tid >> 5, lane = tid & 31;

    int bid = blockIdx.x;
    int gemm = (bid >= TILES_PER_GEMM) ? 1 : 0;
    int r = bid - gemm * TILES_PER_GEMM;
    int n0 = (r >> 2) * BN;
    int m0 = (r & 3) * BM;

    const __half* B = gemm ? d_Br16 : d_Bl16;
    float* C = gemm ? d_xr : d_xl;
    const float* bias = gemm ? biasR : biasL;

    // warp tile 32 (M) x 64 (N): 4 warps in M, 2 warps in N
    int wm = (wid & 3) * 32;
    int wn = (wid >> 2) * 64;

    uint32_t stg[NSTAGE];
#pragma unroll
    for (int s = 0; s < NSTAGE; s++) stg[s] = sbase + s * STAGE_BYTES;

    float acc[2][8][4];
#pragma unroll
    for (int mf = 0; mf < 2; mf++)
#pragma unroll
        for (int nf = 0; nf < 8; nf++)
#pragma unroll
            for (int q = 0; q < 4; q++) acc[mf][nf][q] = 0.0f;

    load_stage(stg[0], m0, n0, 0, B, tid);
    CP_COMMIT();
    load_stage(stg[1], m0, n0, BK, B, tid);
    CP_COMMIT();

    uint32_t a_lrow = (lane & 7) + ((lane >> 3) & 1) * 8;
    uint32_t a_kadd = (lane >> 4) * 16;
    uint32_t b_lrow = (lane & 7) + ((lane >> 3) & 1) * 8;
    uint32_t b_nadd = (lane >> 4) * 16;

    for (int kt = 0; kt < NK; kt++) {
        if (kt + 2 < NK) { CP_WAIT1(); } else { CP_WAIT0(); }
        __syncthreads();
        if (kt + 2 < NK) {
            load_stage(stg[(kt + 2) % NSTAGE], m0, n0, (kt + 2) * BK, B, tid);
            CP_COMMIT();
        }
        uint32_t st = stg[kt % NSTAGE];
#pragma unroll
        for (int kk = 0; kk < BK; kk += 16) {
            uint32_t ahi[2][4], alo[2][4], bh[8][2];
            uint32_t abase = st + (wm + a_lrow) * A_STRIDE + kk * 2 + a_kadd;
#pragma unroll
            for (int mf = 0; mf < 2; mf++) {
                uint32_t ad = abase + mf * 16 * A_STRIDE;
                LDSM_X4(ahi[mf][0], ahi[mf][1], ahi[mf][2], ahi[mf][3], ad + OFF_AHI);
                LDSM_X4(alo[mf][0], alo[mf][1], alo[mf][2], alo[mf][3], ad + OFF_ALO);
            }
            uint32_t bbase = st + OFF_BH + (kk + b_lrow) * B_STRIDE + wn * 2 + b_nadd;
#pragma unroll
            for (int c = 0; c < 4; c++) {
                LDSM_X4T(bh[2 * c][0], bh[2 * c][1], bh[2 * c + 1][0], bh[2 * c + 1][1],
                         bbase + c * 32);
            }
#pragma unroll
            for (int mf = 0; mf < 2; mf++)
#pragma unroll
                for (int nf = 0; nf < 8; nf++) {
                    MMA16816F16(acc[mf][nf], ahi[mf], bh[nf]);
                    MMA16816F16(acc[mf][nf], alo[mf], bh[nf]);
                }
        }
    }

    // epilogue
    int g = lane >> 2, tc = lane & 3;
#pragma unroll
    for (int mf = 0; mf < 2; mf++) {
#pragma unroll
        for (int nf = 0; nf < 8; nf++) {
            int row = m0 + wm + mf * 16 + g;
            int col = n0 + wn + nf * 8 + tc * 2;
            float b0 = bias[col], b1 = bias[col + 1];
            float2 v0 = make_float2(acc[mf][nf][0] + b0, acc[mf][nf][1] + b1);
            float2 v1 = make_float2(acc[mf][nf][2] + b0, acc[mf][nf][3] + b1);
            *(float2*)(C + (size_t)row * HF + col) = v0;
            *(float2*)(C + (size_t)(row + 8) * HF + col) = v1;
        }
    }
}

// ---------------- stage 3: fused logits + segment softmax (per dst) ----------
__global__ void __launch_bounds__(256)
logits_softmax_kernel(const float* __restrict__ att) {
    extern __shared__ float sm[];
    float* s_xr = sm;                 // HF floats
    float* s_lg = sm + HF;            // [HH][LS_CAP]
    int n = blockIdx.x, tid = threadIdx.x;
    int s0 = d_rowptr[n];
    int cnt = d_rowptr[n + 1] - s0;
    if (cnt > LS_CAP) cnt = LS_CAP;

    {
        const float4* xr = (const float4*)(d_xr + (size_t)n * HF);
        float4* sx = (float4*)s_xr;
        for (int i = tid; i < HF / 4; i += 256) sx[i] = xr[i];
    }
    __syncthreads();

    int wid = tid >> 5, lane = tid & 31;
    int h = wid & 3, ep = wid >> 2;
    for (int si = ep; si < cnt; si += 2) {
        int src = d_esrc[s0 + si];
        const float4* pl = (const float4*)(d_xl + (size_t)src * HF + h * FF);
        const float4* pr = (const float4*)(s_xr + h * FF);
        const float4* pa = (const float4*)(att + h * FF);
        float s = 0.0f;
#pragma unroll 4
        for (int it = 0; it < 24; it++) {
            int idx = lane + it * 32;
            float4 a = pl[idx];
            float4 b = pr[idx];
            float4 w = pa[idx];
            float z;
            z = a.x + b.x; s += w.x * (z > 0.0f ? z : SLOPE * z);
            z = a.y + b.y; s += w.y * (z > 0.0f ? z : SLOPE * z);
            z = a.z + b.z; s += w.z * (z > 0.0f ? z : SLOPE * z);
            z = a.w + b.w; s += w.w * (z > 0.0f ? z : SLOPE * z);
        }
#pragma unroll
        for (int o = 16; o; o >>= 1) s += __shfl_xor_sync(0xFFFFFFFFu, s, o);
        if (lane == 0) s_lg[h * LS_CAP + si] = s;
    }
    __syncthreads();

    if (wid < 4) {
        float* lg = s_lg + wid * LS_CAP;
        float mx = -INFINITY;
        for (int si = lane; si < cnt; si += 32) mx = fmaxf(mx, lg[si]);
#pragma unroll
        for (int o = 16; o; o >>= 1) mx = fmaxf(mx, __shfl_xor_sync(0xFFFFFFFFu, mx, o));
        float den = 0.0f;
        for (int si = lane; si < cnt; si += 32) {
            float ex = expf(lg[si] - mx);
            lg[si] = ex;
            den += ex;
        }
#pragma unroll
        for (int o = 16; o; o >>= 1) den += __shfl_xor_sync(0xFFFFFFFFu, den, o);
        float inv = 1.0f / den;
        for (int si = lane; si < cnt; si += 32)
            d_alpha[(s0 + si) * HH + wid] = lg[si] * inv;
    }
}

// ---------------- stage 5: aggregation ---------------------------------------
__global__ void __launch_bounds__(256)
agg_kernel() {
    __shared__ int   s_src[128];
    __shared__ float s_al[HH][128];
    int n = blockIdx.x, tid = threadIdx.x;
    int s0 = d_rowptr[n], s1 = d_rowptr[n + 1];

    float4 acc[12];
#pragma unroll
    for (int j = 0; j < 12; j++) acc[j] = make_float4(0.f, 0.f, 0.f, 0.f);

    for (int base = s0; base < s1; base += 128) {
        int cnt = min(128, s1 - base);
        __syncthreads();
        if (tid < cnt) {
            s_src[tid] = d_esrc[base + tid];
            float4 a = *(const float4*)(d_alpha + (size_t)(base + tid) * HH);
            s_al[0][tid] = a.x; s_al[1][tid] = a.y;
            s_al[2][tid] = a.z; s_al[3][tid] = a.w;
        }
        __syncthreads();
        for (int s = 0; s < cnt; s++) {
            const float4* row = (const float4*)(d_xl + (size_t)s_src[s] * HF);
            float al0 = s_al[0][s], al1 = s_al[1][s], al2 = s_al[2][s], al3 = s_al[3][s];
#pragma unroll
            for (int j = 0; j < 12; j++) {
                float al = (j < 3) ? al0 : (j < 6) ? al1 : (j < 9) ? al2 : al3;
                float4 v = row[j * 256 + tid];
                acc[j].x += al * v.x;
                acc[j].y += al * v.y;
                acc[j].z += al * v.z;
                acc[j].w += al * v.w;
            }
        }
    }

#pragma unroll
    for (int j = 0; j < 12; j++)
        *(float4*)(d_agg + (size_t)n * HF + (j * 256 + tid) * 4) = acc[j];
}

// ---------------- stage 6: fc2+BN2+residual + FFN (fused) --------------------
__global__ void final_kernel(const float* __restrict__ x,
                             const float* __restrict__ gat_b,
                             const float* __restrict__ fc2W, const float* __restrict__ fc2b,
                             const float* __restrict__ b2g, const float* __restrict__ b2b,
                             const float* __restrict__ b2m, const float* __restrict__ b2v,
                             const float* __restrict__ f1W, const float* __restrict__ f1b,
                             const float* __restrict__ bf1g, const float* __restrict__ bf1b,
                             const float* __restrict__ bf1m, const float* __restrict__ bf1v,
                             const float* __restrict__ f2W, const float* __restrict__ f2b,
                             const float* __restrict__ bf2g, const float* __restrict__ bf2b,
                             const float* __restrict__ bf2m, const float* __restrict__ bf2v,
                             float* __restrict__ out) {
    int n = blockIdx.x;
    int p = blockIdx.y * 256 + threadIdx.x;

    float ch[HH * CC];
#pragma unroll
    for (int h = 0; h < HH; h++)
#pragma unroll
        for (int c = 0; c < CC; c++)
            ch[h * CC + c] = d_agg[(size_t)n * HF + h * FF + c * PIX + p]
                           + gat_b[h * FF + c * PIX + p];

    float gv[CC];
#pragma unroll
    for (int oc = 0; oc < CC; oc++) {
        float t = fc2b[oc];
#pragma unroll
        for (int k = 0; k < HH * CC; k++) t += fc2W[oc * (HH * CC) + k] * ch[k];
        float inv = b2g[oc] * rsqrtf(b2v[oc] + BEPS);
        gv[oc] = t * inv + b2b[oc] - b2m[oc] * inv + x[(size_t)n * FF + oc * PIX + p];
    }
    float f1[CC];
#pragma unroll
    for (int oc = 0; oc < CC; oc++) {
        float t = f1b[oc];
#pragma unroll
        for (int ic = 0; ic < CC; ic++) t += f1W[oc * CC + ic] * gv[ic];
        float inv = bf1g[oc] * rsqrtf(bf1v[oc] + BEPS);
        float val = t * inv + bf1b[oc] - bf1m[oc] * inv;
        f1[oc] = val > 0.0f ? val : 0.0f;
    }
#pragma unroll
    for (int oc = 0; oc < CC; oc++) {
        float t = f2b[oc];
#pragma unroll
        for (int ic = 0; ic < CC; ic++) t += f2W[oc * CC + ic] * f1[ic];
        float inv = bf2g[oc] * rsqrtf(bf2v[oc] + BEPS);
        float val = t * inv + bf2b[oc] - bf2m[oc] * inv;
        out[(size_t)n * FF + oc * PIX + p] = val + gv[oc];
    }
}

// ---------------- launch -----------------------------------------------------
extern "C" void kernel_launch(void* const* d_in, const int* in_sizes, int n_in,
                              void* d_out, int out_size) {
    const float* x     = (const float*)d_in[0];
    const int*   ei    = (const int*)d_in[1];
    const float* fc1W  = (const float*)d_in[2];
    const float* fc1b  = (const float*)d_in[3];
    const float* b1g   = (const float*)d_in[4];
    const float* b1b   = (const float*)d_in[5];
    const float* b1m   = (const float*)d_in[6];
    const float* b1v   = (const float*)d_in[7];
    const float* Wl    = (const float*)d_in[8];
    const float* bl    = (const float*)d_in[9];
    const float* Wr    = (const float*)d_in[10];
    const float* br    = (const float*)d_in[11];
    const float* att   = (const float*)d_in[12];
    const float* gat_b = (const float*)d_in[13];
    const float* fc2W  = (const float*)d_in[14];
    const float* fc2b  = (const float*)d_in[15];
    const float* b2g   = (const float*)d_in[16];
    const float* b2b   = (const float*)d_in[17];
    const float* b2m   = (const float*)d_in[18];
    const float* b2v   = (const float*)d_in[19];
    const float* f1W   = (const float*)d_in[20];
    const float* f1b   = (const float*)d_in[21];
    const float* bf1g  = (const float*)d_in[22];
    const float* bf1b  = (const float*)d_in[23];
    const float* bf1m  = (const float*)d_in[24];
    const float* bf1v  = (const float*)d_in[25];
    const float* f2W   = (const float*)d_in[26];
    const float* f2b   = (const float*)d_in[27];
    const float* bf2g  = (const float*)d_in[28];
    const float* bf2b  = (const float*)d_in[29];
    const float* bf2m  = (const float*)d_in[30];
    const float* bf2v  = (const float*)d_in[31];
    float* out = (float*)d_out;

    cudaFuncSetAttribute(mmagemm_kernel, cudaFuncAttributeMaxDynamicSharedMemorySize, SMEM_TOTAL);
    cudaFuncSetAttribute(logits_softmax_kernel, cudaFuncAttributeMaxDynamicSharedMemorySize, LS_SMEM);

    wconv_kernel<<<dim3((FF * HF) / (256 * 8), 2), 256>>>(Wl, Wr);
    fc1_bn_kernel<<<dim3(NN, 4), 256>>>(x, fc1W, fc1b, b1g, b1b, b1m, b1v);
    csr_kernel<<<1, NN>>>(ei);
    mmagemm_kernel<<<2 * TILES_PER_GEMM, 256, SMEM_TOTAL>>>(bl, br);
    logits_softmax_kernel<<<NN, 256, LS_SMEM>>>(att);
    agg_kernel<<<NN, 256>>>();
    final_kernel<<<dim3(NN, 4), 256>>>(x, gat_b, fc2W, fc2b, b2g, b2b, b2m, b2v,
                                       f1W, f1b, bf1g, bf1b, bf1m, bf1v,
                                       f2W, f2b, bf2g, bf2b, bf2m, bf2v, out);
}

// round 8
// speedup vs baseline: 2.1142x; 1.4093x over previous
#include <cuda_runtime.h>
#include <cuda_bf16.h>
#include <cuda_fp16.h>
#include <math.h>
#include <stdint.h>

#define NN 512
#define CC 3
#define PIX 1024
#define FF 3072          // K dim
#define HH 4
#define HF 12288         // N dim
#define EE 4096
#define ET 4608
#define BEPS 1e-5f
#define SLOPE 0.2f

// GEMM tiling
#define BM 128
#define BN 128
#define BK 32
#define NK (FF / BK)             // 96
#define TILES_PER_GEMM ((NN / BM) * (HF / BN))   // 384

// smem stage layout (fp16, padded rows for conflict-free ldmatrix)
#define A_STRIDE 80              // 32 halves = 64 B + 16 pad
#define B_STRIDE 272             // 128 halves = 256 B + 16 pad
#define OFF_A 0
#define OFF_BH (BM * A_STRIDE)                   // 10240
#define STAGE_BYTES (OFF_BH + BK * B_STRIDE)     // 18944
#define NSTAGE 3
#define SMEM_TOTAL (NSTAGE * STAGE_BYTES)        // 56832

// logits kernel smem: xr cache + logits buffer
#define LS_CAP 128
#define LS_SMEM (HF * 4 + HH * LS_CAP * 4)       // 51200

// ---------------- scratch ----------------------------------------------------
__device__ __half d_Ah[NN * FF];
__device__ __half d_Bl16[(size_t)FF * HF];
__device__ __half d_Br16[(size_t)FF * HF];
__device__ float d_xl[(size_t)NN * HF];
__device__ float d_xr[(size_t)NN * HF];
__device__ float d_alpha[ET * HH];
__device__ float d_agg[(size_t)NN * HF];
__device__ int   d_rowptr[NN + 1];
__device__ int   d_esrc[ET];

// ---------------- PTX helpers ------------------------------------------------
__device__ __forceinline__ uint32_t smem_to_u32(const void* p) {
    uint32_t a;
    asm("{ .reg .u64 t; cvta.to.shared.u64 t, %1; cvt.u32.u64 %0, t; }" : "=r"(a) : "l"(p));
    return a;
}
__device__ __forceinline__ void cpa16(uint32_t dst, const void* src) {
    asm volatile("cp.async.cg.shared.global [%0], [%1], 16;" :: "r"(dst), "l"(src));
}
#define CP_COMMIT() asm volatile("cp.async.commit_group;" ::: "memory")
#define CP_WAIT0()  asm volatile("cp.async.wait_group 0;" ::: "memory")
#define CP_WAIT1()  asm volatile("cp.async.wait_group 1;" ::: "memory")

#define LDSM_X4(r0, r1, r2, r3, addr) \
    asm volatile("ldmatrix.sync.aligned.m8n8.x4.shared.b16 {%0,%1,%2,%3}, [%4];" \
        : "=r"(r0), "=r"(r1), "=r"(r2), "=r"(r3) : "r"(addr))
#define LDSM_X4T(r0, r1, r2, r3, addr) \
    asm volatile("ldmatrix.sync.aligned.m8n8.x4.trans.shared.b16 {%0,%1,%2,%3}, [%4];" \
        : "=r"(r0), "=r"(r1), "=r"(r2), "=r"(r3) : "r"(addr))

#define MMA16816F16(d, a, b) \
    asm volatile("mma.sync.aligned.m16n8k16.row.col.f32.f16.f16.f32 " \
        "{%0,%1,%2,%3}, {%4,%5,%6,%7}, {%8,%9}, {%0,%1,%2,%3};" \
        : "+f"((d)[0]), "+f"((d)[1]), "+f"((d)[2]), "+f"((d)[3]) \
        : "r"((a)[0]), "r"((a)[1]), "r"((a)[2]), "r"((a)[3]), "r"((b)[0]), "r"((b)[1]))

// ---------------- misc -------------------------------------------------------
__device__ __forceinline__ int edge_src(const int* ei, int e) { return (e < EE) ? ei[e] : (e - EE); }
__device__ __forceinline__ int edge_dst(const int* ei, int e) { return (e < EE) ? ei[EE + e] : (e - EE); }

// ---------------- stage 1: fc1 + BN1 -> fp16 ---------------------------------
__global__ void fc1_bn_kernel(const float* __restrict__ x,
                              const float* __restrict__ W,
                              const float* __restrict__ b,
                              const float* __restrict__ bg,
                              const float* __restrict__ bb,
                              const float* __restrict__ bm,
                              const float* __restrict__ bv) {
    int n = blockIdx.x;
    int p = blockIdx.y * 256 + threadIdx.x;
    float xin[CC];
#pragma unroll
    for (int c = 0; c < CC; c++) xin[c] = x[(size_t)n * FF + c * PIX + p];
#pragma unroll
    for (int oc = 0; oc < CC; oc++) {
        float t = b[oc];
#pragma unroll
        for (int ic = 0; ic < CC; ic++) t += W[oc * CC + ic] * xin[ic];
        float inv = bg[oc] * rsqrtf(bv[oc] + BEPS);
        float hv = t * inv + bb[oc] - bm[oc] * inv;
        d_Ah[(size_t)n * FF + oc * PIX + p] = __float2half_rn(hv);
    }
}

// ---------------- weight fp32 -> fp16 convert (streaming) --------------------
__global__ void wconv_kernel(const float* __restrict__ Wl, const float* __restrict__ Wr) {
    const float* W = blockIdx.y ? Wr : Wl;
    __half* B = blockIdx.y ? d_Br16 : d_Bl16;
    size_t i = ((size_t)blockIdx.x * 256 + threadIdx.x) * 8;
    float4 v0 = *(const float4*)(W + i);
    float4 v1 = *(const float4*)(W + i + 4);
    __half2 h[4];
    h[0] = __floats2half2_rn(v0.x, v0.y);
    h[1] = __floats2half2_rn(v0.z, v0.w);
    h[2] = __floats2half2_rn(v1.x, v1.y);
    h[3] = __floats2half2_rn(v1.z, v1.w);
    *(uint4*)(B + i) = *(uint4*)h;
}

// ---------------- CSR build: init + deg + scan + scatter, one CTA ------------
__global__ void __launch_bounds__(512)
csr_kernel(const int* __restrict__ ei) {
    __shared__ int sdeg[NN];
    __shared__ int sscan[NN];
    __shared__ int scur[NN];
    int t = threadIdx.x;
    sdeg[t] = 0;
    __syncthreads();
    for (int e = t; e < ET; e += NN) atomicAdd(&sdeg[edge_dst(ei, e)], 1);
    __syncthreads();
    sscan[t] = sdeg[t];
    __syncthreads();
    for (int o = 1; o < NN; o <<= 1) {
        int v = (t >= o) ? sscan[t - o] : 0;
        __syncthreads();
        sscan[t] += v;
        __syncthreads();
    }
    if (t == 0) d_rowptr[0] = 0;
    d_rowptr[t + 1] = sscan[t];
    scur[t] = sscan[t] - sdeg[t];
    __syncthreads();
    for (int e = t; e < ET; e += NN) {
        int slot = atomicAdd(&scur[edge_dst(ei, e)], 1);
        d_esrc[slot] = edge_src(ei, e);
    }
}

// ---------------- stage 2: HMMA GEMM (fp16 single pass, warp tile 32x64) -----
__device__ __forceinline__ void load_stage(uint32_t st, int m0, int n0, int k0,
                                           const __half* __restrict__ B, int tid) {
#pragma unroll
    for (int i = tid; i < 512; i += 256) {
        int row = i >> 2, c = i & 3;
        uint32_t off = row * A_STRIDE + c * 16;
        size_t g = (size_t)(m0 + row) * FF + k0 + c * 8;
        cpa16(st + OFF_A + off, d_Ah + g);
    }
#pragma unroll
    for (int i = tid; i < 512; i += 256) {
        int row = i >> 4, c = i & 15;
        uint32_t off = row * B_STRIDE + c * 16;
        size_t g = (size_t)(k0 + row) * HF + n0 + c * 8;
        cpa16(st + OFF_BH + off, B + g);
    }
}

__global__ void __launch_bounds__(256)
mmagemm_kernel(const float* __restrict__ biasL, const float* __restrict__ biasR) {
    extern __shared__ __align__(1024) char smem[];
    uint32_t sbase = smem_to_u32(smem);
    int tid = threadIdx.x;
    int wid = tid >> 5, lane = tid & 31;

    int bid = blockIdx.x;
    int gemm = (bid >= TILES_PER_GEMM) ? 1 : 0;
    int r = bid - gemm * TILES_PER_GEMM;
    int n0 = (r >> 2) * BN;
    int m0 = (r & 3) * BM;

    const __half* B = gemm ? d_Br16 : d_Bl16;
    float* C = gemm ? d_xr : d_xl;
    const float* bias = gemm ? biasR : biasL;

    // warp tile 32 (M) x 64 (N): 4 warps in M, 2 warps in N
    int wm = (wid & 3) * 32;
    int wn = (wid >> 2) * 64;

    uint32_t stg[NSTAGE];
#pragma unroll
    for (int s = 0; s < NSTAGE; s++) stg[s] = sbase + s * STAGE_BYTES;

    float acc[2][8][4];
#pragma unroll
    for (int mf = 0; mf < 2; mf++)
#pragma unroll
        for (int nf = 0; nf < 8; nf++)
#pragma unroll
            for (int q = 0; q < 4; q++) acc[mf][nf][q] = 0.0f;

    load_stage(stg[0], m0, n0, 0, B, tid);
    CP_COMMIT();
    load_stage(stg[1], m0, n0, BK, B, tid);
    CP_COMMIT();

    uint32_t a_lrow = (lane & 7) + ((lane >> 3) & 1) * 8;
    uint32_t a_kadd = (lane >> 4) * 16;
    uint32_t b_lrow = (lane & 7) + ((lane >> 3) & 1) * 8;
    uint32_t b_nadd = (lane >> 4) * 16;

    for (int kt = 0; kt < NK; kt++) {
        if (kt + 2 < NK) { CP_WAIT1(); } else { CP_WAIT0(); }
        __syncthreads();
        if (kt + 2 < NK) {
            load_stage(stg[(kt + 2) % NSTAGE], m0, n0, (kt + 2) * BK, B, tid);
            CP_COMMIT();
        }
        uint32_t st = stg[kt % NSTAGE];
#pragma unroll
        for (int kk = 0; kk < BK; kk += 16) {
            uint32_t ah[2][4], bh[8][2];
            uint32_t abase = st + OFF_A + (wm + a_lrow) * A_STRIDE + kk * 2 + a_kadd;
#pragma unroll
            for (int mf = 0; mf < 2; mf++) {
                uint32_t ad = abase + mf * 16 * A_STRIDE;
                LDSM_X4(ah[mf][0], ah[mf][1], ah[mf][2], ah[mf][3], ad);
            }
            uint32_t bbase = st + OFF_BH + (kk + b_lrow) * B_STRIDE + wn * 2 + b_nadd;
#pragma unroll
            for (int c = 0; c < 4; c++) {
                LDSM_X4T(bh[2 * c][0], bh[2 * c][1], bh[2 * c + 1][0], bh[2 * c + 1][1],
                         bbase + c * 32);
            }
#pragma unroll
            for (int mf = 0; mf < 2; mf++)
#pragma unroll
                for (int nf = 0; nf < 8; nf++)
                    MMA16816F16(acc[mf][nf], ah[mf], bh[nf]);
        }
    }

    // epilogue
    int g = lane >> 2, tc = lane & 3;
#pragma unroll
    for (int mf = 0; mf < 2; mf++) {
#pragma unroll
        for (int nf = 0; nf < 8; nf++) {
            int row = m0 + wm + mf * 16 + g;
            int col = n0 + wn + nf * 8 + tc * 2;
            float b0 = bias[col], b1 = bias[col + 1];
            float2 v0 = make_float2(acc[mf][nf][0] + b0, acc[mf][nf][1] + b1);
            float2 v1 = make_float2(acc[mf][nf][2] + b0, acc[mf][nf][3] + b1);
            *(float2*)(C + (size_t)row * HF + col) = v0;
            *(float2*)(C + (size_t)(row + 8) * HF + col) = v1;
        }
    }
}

// ---------------- stage 3: fused logits + segment softmax (per dst) ----------
__global__ void __launch_bounds__(256)
logits_softmax_kernel(const float* __restrict__ att) {
    extern __shared__ float sm[];
    float* s_xr = sm;                 // HF floats
    float* s_lg = sm + HF;            // [HH][LS_CAP]
    int n = blockIdx.x, tid = threadIdx.x;
    int s0 = d_rowptr[n];
    int cnt = d_rowptr[n + 1] - s0;
    if (cnt > LS_CAP) cnt = LS_CAP;

    {
        const float4* xr = (const float4*)(d_xr + (size_t)n * HF);
        float4* sx = (float4*)s_xr;
        for (int i = tid; i < HF / 4; i += 256) sx[i] = xr[i];
    }
    __syncthreads();

    int wid = tid >> 5, lane = tid & 31;
    int h = wid & 3, ep = wid >> 2;
    for (int si = ep; si < cnt; si += 2) {
        int src = d_esrc[s0 + si];
        const float4* pl = (const float4*)(d_xl + (size_t)src * HF + h * FF);
        const float4* pr = (const float4*)(s_xr + h * FF);
        const float4* pa = (const float4*)(att + h * FF);
        float s = 0.0f;
#pragma unroll 4
        for (int it = 0; it < 24; it++) {
            int idx = lane + it * 32;
            float4 a = pl[idx];
            float4 b = pr[idx];
            float4 w = pa[idx];
            float z;
            z = a.x + b.x; s += w.x * (z > 0.0f ? z : SLOPE * z);
            z = a.y + b.y; s += w.y * (z > 0.0f ? z : SLOPE * z);
            z = a.z + b.z; s += w.z * (z > 0.0f ? z : SLOPE * z);
            z = a.w + b.w; s += w.w * (z > 0.0f ? z : SLOPE * z);
        }
#pragma unroll
        for (int o = 16; o; o >>= 1) s += __shfl_xor_sync(0xFFFFFFFFu, s, o);
        if (lane == 0) s_lg[h * LS_CAP + si] = s;
    }
    __syncthreads();

    if (wid < 4) {
        float* lg = s_lg + wid * LS_CAP;
        float mx = -INFINITY;
        for (int si = lane; si < cnt; si += 32) mx = fmaxf(mx, lg[si]);
#pragma unroll
        for (int o = 16; o; o >>= 1) mx = fmaxf(mx, __shfl_xor_sync(0xFFFFFFFFu, mx, o));
        float den = 0.0f;
        for (int si = lane; si < cnt; si += 32) {
            float ex = expf(lg[si] - mx);
            lg[si] = ex;
            den += ex;
        }
#pragma unroll
        for (int o = 16; o; o >>= 1) den += __shfl_xor_sync(0xFFFFFFFFu, den, o);
        float inv = 1.0f / den;
        for (int si = lane; si < cnt; si += 32)
            d_alpha[(s0 + si) * HH + wid] = lg[si] * inv;
    }
}

// ---------------- stage 5: aggregation ---------------------------------------
__global__ void __launch_bounds__(256)
agg_kernel() {
    __shared__ int   s_src[128];
    __shared__ float s_al[HH][128];
    int n = blockIdx.x, tid = threadIdx.x;
    int s0 = d_rowptr[n], s1 = d_rowptr[n + 1];

    float4 acc[12];
#pragma unroll
    for (int j = 0; j < 12; j++) acc[j] = make_float4(0.f, 0.f, 0.f, 0.f);

    for (int base = s0; base < s1; base += 128) {
        int cnt = min(128, s1 - base);
        __syncthreads();
        if (tid < cnt) {
            s_src[tid] = d_esrc[base + tid];
            float4 a = *(const float4*)(d_alpha + (size_t)(base + tid) * HH);
            s_al[0][tid] = a.x; s_al[1][tid] = a.y;
            s_al[2][tid] = a.z; s_al[3][tid] = a.w;
        }
        __syncthreads();
        for (int s = 0; s < cnt; s++) {
            const float4* row = (const float4*)(d_xl + (size_t)s_src[s] * HF);
            float al0 = s_al[0][s], al1 = s_al[1][s], al2 = s_al[2][s], al3 = s_al[3][s];
#pragma unroll
            for (int j = 0; j < 12; j++) {
                float al = (j < 3) ? al0 : (j < 6) ? al1 : (j < 9) ? al2 : al3;
                float4 v = row[j * 256 + tid];
                acc[j].x += al * v.x;
                acc[j].y += al * v.y;
                acc[j].z += al * v.z;
                acc[j].w += al * v.w;
            }
        }
    }

#pragma unroll
    for (int j = 0; j < 12; j++)
        *(float4*)(d_agg + (size_t)n * HF + (j * 256 + tid) * 4) = acc[j];
}

// ---------------- stage 6: fc2+BN2+residual + FFN (fused) --------------------
__global__ void final_kernel(const float* __restrict__ x,
                             const float* __restrict__ gat_b,
                             const float* __restrict__ fc2W, const float* __restrict__ fc2b,
                             const float* __restrict__ b2g, const float* __restrict__ b2b,
                             const float* __restrict__ b2m, const float* __restrict__ b2v,
                             const float* __restrict__ f1W, const float* __restrict__ f1b,
                             const float* __restrict__ bf1g, const float* __restrict__ bf1b,
                             const float* __restrict__ bf1m, const float* __restrict__ bf1v,
                             const float* __restrict__ f2W, const float* __restrict__ f2b,
                             const float* __restrict__ bf2g, const float* __restrict__ bf2b,
                             const float* __restrict__ bf2m, const float* __restrict__ bf2v,
                             float* __restrict__ out) {
    int n = blockIdx.x;
    int p = blockIdx.y * 256 + threadIdx.x;

    float ch[HH * CC];
#pragma unroll
    for (int h = 0; h < HH; h++)
#pragma unroll
        for (int c = 0; c < CC; c++)
            ch[h * CC + c] = d_agg[(size_t)n * HF + h * FF + c * PIX + p]
                           + gat_b[h * FF + c * PIX + p];

    float gv[CC];
#pragma unroll
    for (int oc = 0; oc < CC; oc++) {
        float t = fc2b[oc];
#pragma unroll
        for (int k = 0; k < HH * CC; k++) t += fc2W[oc * (HH * CC) + k] * ch[k];
        float inv = b2g[oc] * rsqrtf(b2v[oc] + BEPS);
        gv[oc] = t * inv + b2b[oc] - b2m[oc] * inv + x[(size_t)n * FF + oc * PIX + p];
    }
    float f1[CC];
#pragma unroll
    for (int oc = 0; oc < CC; oc++) {
        float t = f1b[oc];
#pragma unroll
        for (int ic = 0; ic < CC; ic++) t += f1W[oc * CC + ic] * gv[ic];
        float inv = bf1g[oc] * rsqrtf(bf1v[oc] + BEPS);
        float val = t * inv + bf1b[oc] - bf1m[oc] * inv;
        f1[oc] = val > 0.0f ? val : 0.0f;
    }
#pragma unroll
    for (int oc = 0; oc < CC; oc++) {
        float t = f2b[oc];
#pragma unroll
        for (int ic = 0; ic < CC; ic++) t += f2W[oc * CC + ic] * f1[ic];
        float inv = bf2g[oc] * rsqrtf(bf2v[oc] + BEPS);
        float val = t * inv + bf2b[oc] - bf2m[oc] * inv;
        out[(size_t)n * FF + oc * PIX + p] = val + gv[oc];
    }
}

// ---------------- launch -----------------------------------------------------
extern "C" void kernel_launch(void* const* d_in, const int* in_sizes, int n_in,
                              void* d_out, int out_size) {
    const float* x     = (const float*)d_in[0];
    const int*   ei    = (const int*)d_in[1];
    const float* fc1W  = (const float*)d_in[2];
    const float* fc1b  = (const float*)d_in[3];
    const float* b1g   = (const float*)d_in[4];
    const float* b1b   = (const float*)d_in[5];
    const float* b1m   = (const float*)d_in[6];
    const float* b1v   = (const float*)d_in[7];
    const float* Wl    = (const float*)d_in[8];
    const float* bl    = (const float*)d_in[9];
    const float* Wr    = (const float*)d_in[10];
    const float* br    = (const float*)d_in[11];
    const float* att   = (const float*)d_in[12];
    const float* gat_b = (const float*)d_in[13];
    const float* fc2W  = (const float*)d_in[14];
    const float* fc2b  = (const float*)d_in[15];
    const float* b2g   = (const float*)d_in[16];
    const float* b2b   = (const float*)d_in[17];
    const float* b2m   = (const float*)d_in[18];
    const float* b2v   = (const float*)d_in[19];
    const float* f1W   = (const float*)d_in[20];
    const float* f1b   = (const float*)d_in[21];
    const float* bf1g  = (const float*)d_in[22];
    const float* bf1b  = (const float*)d_in[23];
    const float* bf1m  = (const float*)d_in[24];
    const float* bf1v  = (const float*)d_in[25];
    const float* f2W   = (const float*)d_in[26];
    const float* f2b   = (const float*)d_in[27];
    const float* bf2g  = (const float*)d_in[28];
    const float* bf2b  = (const float*)d_in[29];
    const float* bf2m  = (const float*)d_in[30];
    const float* bf2v  = (const float*)d_in[31];
    float* out = (float*)d_out;

    cudaFuncSetAttribute(mmagemm_kernel, cudaFuncAttributeMaxDynamicSharedMemorySize, SMEM_TOTAL);
    cudaFuncSetAttribute(logits_softmax_kernel, cudaFuncAttributeMaxDynamicSharedMemorySize, LS_SMEM);

    wconv_kernel<<<dim3((FF * HF) / (256 * 8), 2), 256>>>(Wl, Wr);
    fc1_bn_kernel<<<dim3(NN, 4), 256>>>(x, fc1W, fc1b, b1g, b1b, b1m, b1v);
    csr_kernel<<<1, NN>>>(ei);
    mmagemm_kernel<<<2 * TILES_PER_GEMM, 256, SMEM_TOTAL>>>(bl, br);
    logits_softmax_kernel<<<NN, 256, LS_SMEM>>>(att);
    agg_kernel<<<NN, 256>>>();
    final_kernel<<<dim3(NN, 4), 256>>>(x, gat_b, fc2W, fc2b, b2g, b2b, b2m, b2v,
                                       f1W, f1b, bf1g, bf1b, bf1m, bf1v,
                                       f2W, f2b, bf2g, bf2b, bf2m, bf2v, out);
}

// round 9
// speedup vs baseline: 2.2366x; 1.0579x over previous
#include <cuda_runtime.h>
#include <cuda_bf16.h>
#include <cuda_fp16.h>
#include <math.h>
#include <stdint.h>

#define NN 512
#define CC 3
#define PIX 1024
#define FF 3072          // K dim
#define HH 4
#define HF 12288         // N dim
#define EE 4096
#define ET 4608
#define BEPS 1e-5f
#define SLOPE 0.2f

// GEMM tiling
#define BM 128
#define BN 128
#define BK 64
#define NK (FF / BK)             // 48
#define TILES_PER_GEMM ((NN / BM) * (HF / BN))   // 384

// smem stage layout (fp16, padded rows for conflict-free ldmatrix)
#define A_STRIDE 144             // 64 halves = 128 B + 16 pad
#define B_STRIDE 272             // 128 halves = 256 B + 16 pad
#define OFF_A 0
#define OFF_BH (BM * A_STRIDE)                   // 18432
#define STAGE_BYTES (OFF_BH + BK * B_STRIDE)     // 35840
#define NSTAGE 2
#define SMEM_TOTAL (NSTAGE * STAGE_BYTES)        // 71680 -> 2 CTAs/SM

// logits kernel smem: xr cache + logits buffer
#define LS_CAP 128
#define LS_SMEM (HF * 4 + HH * LS_CAP * 4)       // 51200

// ---------------- scratch ----------------------------------------------------
__device__ __half d_Ah[NN * FF];
__device__ __half d_Bl16[(size_t)FF * HF];
__device__ __half d_Br16[(size_t)FF * HF];
__device__ float d_xl[(size_t)NN * HF];
__device__ float d_xr[(size_t)NN * HF];
__device__ float d_alpha[ET * HH];
__device__ float d_agg[(size_t)NN * HF];
__device__ int   d_rowptr[NN + 1];
__device__ int   d_esrc[ET];

// ---------------- PTX helpers ------------------------------------------------
__device__ __forceinline__ uint32_t smem_to_u32(const void* p) {
    uint32_t a;
    asm("{ .reg .u64 t; cvta.to.shared.u64 t, %1; cvt.u32.u64 %0, t; }" : "=r"(a) : "l"(p));
    return a;
}
__device__ __forceinline__ void cpa16(uint32_t dst, const void* src) {
    asm volatile("cp.async.cg.shared.global [%0], [%1], 16;" :: "r"(dst), "l"(src));
}
#define CP_COMMIT() asm volatile("cp.async.commit_group;" ::: "memory")
#define CP_WAIT0()  asm volatile("cp.async.wait_group 0;" ::: "memory")
#define CP_WAIT1()  asm volatile("cp.async.wait_group 1;" ::: "memory")

#define LDSM_X4(r0, r1, r2, r3, addr) \
    asm volatile("ldmatrix.sync.aligned.m8n8.x4.shared.b16 {%0,%1,%2,%3}, [%4];" \
        : "=r"(r0), "=r"(r1), "=r"(r2), "=r"(r3) : "r"(addr))
#define LDSM_X4T(r0, r1, r2, r3, addr) \
    asm volatile("ldmatrix.sync.aligned.m8n8.x4.trans.shared.b16 {%0,%1,%2,%3}, [%4];" \
        : "=r"(r0), "=r"(r1), "=r"(r2), "=r"(r3) : "r"(addr))

#define MMA16816F16(d, a, b) \
    asm volatile("mma.sync.aligned.m16n8k16.row.col.f32.f16.f16.f32 " \
        "{%0,%1,%2,%3}, {%4,%5,%6,%7}, {%8,%9}, {%0,%1,%2,%3};" \
        : "+f"((d)[0]), "+f"((d)[1]), "+f"((d)[2]), "+f"((d)[3]) \
        : "r"((a)[0]), "r"((a)[1]), "r"((a)[2]), "r"((a)[3]), "r"((b)[0]), "r"((b)[1]))

// ---------------- misc -------------------------------------------------------
__device__ __forceinline__ int edge_src(const int* ei, int e) { return (e < EE) ? ei[e] : (e - EE); }
__device__ __forceinline__ int edge_dst(const int* ei, int e) { return (e < EE) ? ei[EE + e] : (e - EE); }

// ---------------- stage 1: fc1 + BN1 -> fp16 ---------------------------------
__global__ void fc1_bn_kernel(const float* __restrict__ x,
                              const float* __restrict__ W,
                              const float* __restrict__ b,
                              const float* __restrict__ bg,
                              const float* __restrict__ bb,
                              const float* __restrict__ bm,
                              const float* __restrict__ bv) {
    int n = blockIdx.x;
    int p = blockIdx.y * 256 + threadIdx.x;
    float xin[CC];
#pragma unroll
    for (int c = 0; c < CC; c++) xin[c] = x[(size_t)n * FF + c * PIX + p];
#pragma unroll
    for (int oc = 0; oc < CC; oc++) {
        float t = b[oc];
#pragma unroll
        for (int ic = 0; ic < CC; ic++) t += W[oc * CC + ic] * xin[ic];
        float inv = bg[oc] * rsqrtf(bv[oc] + BEPS);
        float hv = t * inv + bb[oc] - bm[oc] * inv;
        d_Ah[(size_t)n * FF + oc * PIX + p] = __float2half_rn(hv);
    }
}

// ---------------- weight fp32 -> fp16 convert (streaming) --------------------
__global__ void wconv_kernel(const float* __restrict__ Wl, const float* __restrict__ Wr) {
    const float* W = blockIdx.y ? Wr : Wl;
    __half* B = blockIdx.y ? d_Br16 : d_Bl16;
    size_t i = ((size_t)blockIdx.x * 256 + threadIdx.x) * 8;
    float4 v0 = *(const float4*)(W + i);
    float4 v1 = *(const float4*)(W + i + 4);
    __half2 h[4];
    h[0] = __floats2half2_rn(v0.x, v0.y);
    h[1] = __floats2half2_rn(v0.z, v0.w);
    h[2] = __floats2half2_rn(v1.x, v1.y);
    h[3] = __floats2half2_rn(v1.z, v1.w);
    *(uint4*)(B + i) = *(uint4*)h;
}

// ---------------- CSR build: init + deg + scan + scatter, one CTA ------------
__global__ void __launch_bounds__(512)
csr_kernel(const int* __restrict__ ei) {
    __shared__ int sdeg[NN];
    __shared__ int sscan[NN];
    __shared__ int scur[NN];
    int t = threadIdx.x;
    sdeg[t] = 0;
    __syncthreads();
    for (int e = t; e < ET; e += NN) atomicAdd(&sdeg[edge_dst(ei, e)], 1);
    __syncthreads();
    sscan[t] = sdeg[t];
    __syncthreads();
    for (int o = 1; o < NN; o <<= 1) {
        int v = (t >= o) ? sscan[t - o] : 0;
        __syncthreads();
        sscan[t] += v;
        __syncthreads();
    }
    if (t == 0) d_rowptr[0] = 0;
    d_rowptr[t + 1] = sscan[t];
    scur[t] = sscan[t] - sdeg[t];
    __syncthreads();
    for (int e = t; e < ET; e += NN) {
        int slot = atomicAdd(&scur[edge_dst(ei, e)], 1);
        d_esrc[slot] = edge_src(ei, e);
    }
}

// ---------------- stage 2: HMMA GEMM (BK=64, frag double-buffered) -----------
__device__ __forceinline__ void load_stage(uint32_t st, int m0, int n0, int k0,
                                           const __half* __restrict__ B, int tid) {
#pragma unroll
    for (int i = tid; i < 1024; i += 256) {
        int row = i >> 3, c = i & 7;
        uint32_t off = row * A_STRIDE + c * 16;
        size_t g = (size_t)(m0 + row) * FF + k0 + c * 8;
        cpa16(st + OFF_A + off, d_Ah + g);
    }
#pragma unroll
    for (int i = tid; i < 1024; i += 256) {
        int row = i >> 4, c = i & 15;
        uint32_t off = row * B_STRIDE + c * 16;
        size_t g = (size_t)(k0 + row) * HF + n0 + c * 8;
        cpa16(st + OFF_BH + off, B + g);
    }
}

__global__ void __launch_bounds__(256, 2)
mmagemm_kernel(const float* __restrict__ biasL, const float* __restrict__ biasR) {
    extern __shared__ __align__(1024) char smem[];
    uint32_t sbase = smem_to_u32(smem);
    int tid = threadIdx.x;
    int wid = tid >> 5, lane = tid & 31;

    int bid = blockIdx.x;
    int gemm = (bid >= TILES_PER_GEMM) ? 1 : 0;
    int r = bid - gemm * TILES_PER_GEMM;
    int n0 = (r >> 2) * BN;
    int m0 = (r & 3) * BM;

    const __half* B = gemm ? d_Br16 : d_Bl16;
    float* C = gemm ? d_xr : d_xl;
    const float* bias = gemm ? biasR : biasL;

    // warp tile 32 (M) x 64 (N): 4 warps in M, 2 warps in N
    int wm = (wid & 3) * 32;
    int wn = (wid >> 2) * 64;

    uint32_t stg[2] = { sbase, sbase + STAGE_BYTES };

    float acc[2][8][4];
#pragma unroll
    for (int mf = 0; mf < 2; mf++)
#pragma unroll
        for (int nf = 0; nf < 8; nf++)
#pragma unroll
            for (int q = 0; q < 4; q++) acc[mf][nf][q] = 0.0f;

    load_stage(stg[0], m0, n0, 0, B, tid);
    CP_COMMIT();
    load_stage(stg[1], m0, n0, BK, B, tid);
    CP_COMMIT();
    CP_WAIT1();
    __syncthreads();

    uint32_t a_lrow = (lane & 7) + ((lane >> 3) & 1) * 8;
    uint32_t a_kadd = (lane >> 4) * 16;
    uint32_t b_lrow = (lane & 7) + ((lane >> 3) & 1) * 8;
    uint32_t b_nadd = (lane >> 4) * 16;

    uint32_t ah[2][2][4], bh[2][8][2];

    for (int kt = 0; kt < NK; kt++) {
        uint32_t st = stg[kt & 1];
        uint32_t abase = st + OFF_A + (wm + a_lrow) * A_STRIDE + a_kadd;
        uint32_t bbase = st + OFF_BH + b_lrow * B_STRIDE + wn * 2 + b_nadd;

        // load frags for kk=0 into buf 0
#pragma unroll
        for (int mf = 0; mf < 2; mf++)
            LDSM_X4(ah[0][mf][0], ah[0][mf][1], ah[0][mf][2], ah[0][mf][3],
                    abase + mf * 16 * A_STRIDE);
#pragma unroll
        for (int c = 0; c < 4; c++)
            LDSM_X4T(bh[0][2 * c][0], bh[0][2 * c][1], bh[0][2 * c + 1][0], bh[0][2 * c + 1][1],
                     bbase + c * 32);

#pragma unroll
        for (int kks = 0; kks < 4; kks++) {
            int cur = kks & 1, nxt = cur ^ 1;
            if (kks < 3) {
                uint32_t ka = (kks + 1) * 32;      // bytes: 16 halves per step
                uint32_t ab = abase + ka;
                uint32_t bb = bbase + (kks + 1) * 16 * B_STRIDE;
#pragma unroll
                for (int mf = 0; mf < 2; mf++)
                    LDSM_X4(ah[nxt][mf][0], ah[nxt][mf][1], ah[nxt][mf][2], ah[nxt][mf][3],
                            ab + mf * 16 * A_STRIDE);
#pragma unroll
                for (int c = 0; c < 4; c++)
                    LDSM_X4T(bh[nxt][2 * c][0], bh[nxt][2 * c][1],
                             bh[nxt][2 * c + 1][0], bh[nxt][2 * c + 1][1],
                             bb + c * 32);
            }
#pragma unroll
            for (int mf = 0; mf < 2; mf++)
#pragma unroll
                for (int nf = 0; nf < 8; nf++)
                    MMA16816F16(acc[mf][nf], ah[cur][mf], bh[cur][nf]);
        }

        __syncthreads();
        if (kt + 2 < NK) {
            load_stage(stg[kt & 1], m0, n0, (kt + 2) * BK, B, tid);
            CP_COMMIT();
        }
        if (kt + 1 < NK) {
            CP_WAIT1();
            __syncthreads();
        }
    }

    // epilogue
    int g = lane >> 2, tc = lane & 3;
#pragma unroll
    for (int mf = 0; mf < 2; mf++) {
#pragma unroll
        for (int nf = 0; nf < 8; nf++) {
            int row = m0 + wm + mf * 16 + g;
            int col = n0 + wn + nf * 8 + tc * 2;
            float b0 = bias[col], b1 = bias[col + 1];
            float2 v0 = make_float2(acc[mf][nf][0] + b0, acc[mf][nf][1] + b1);
            float2 v1 = make_float2(acc[mf][nf][2] + b0, acc[mf][nf][3] + b1);
            *(float2*)(C + (size_t)row * HF + col) = v0;
            *(float2*)(C + (size_t)(row + 8) * HF + col) = v1;
        }
    }
}

// ---------------- stage 3: fused logits + segment softmax (per dst) ----------
__global__ void __launch_bounds__(256)
logits_softmax_kernel(const float* __restrict__ att) {
    extern __shared__ float sm[];
    float* s_xr = sm;                 // HF floats
    float* s_lg = sm + HF;            // [HH][LS_CAP]
    int n = blockIdx.x, tid = threadIdx.x;
    int s0 = d_rowptr[n];
    int cnt = d_rowptr[n + 1] - s0;
    if (cnt > LS_CAP) cnt = LS_CAP;

    {
        const float4* xr = (const float4*)(d_xr + (size_t)n * HF);
        float4* sx = (float4*)s_xr;
        for (int i = tid; i < HF / 4; i += 256) sx[i] = xr[i];
    }
    __syncthreads();

    int wid = tid >> 5, lane = tid & 31;
    int h = wid & 3, ep = wid >> 2;
    for (int si = ep; si < cnt; si += 2) {
        int src = d_esrc[s0 + si];
        const float4* pl = (const float4*)(d_xl + (size_t)src * HF + h * FF);
        const float4* pr = (const float4*)(s_xr + h * FF);
        const float4* pa = (const float4*)(att + h * FF);
        float s = 0.0f;
#pragma unroll 4
        for (int it = 0; it < 24; it++) {
            int idx = lane + it * 32;
            float4 a = pl[idx];
            float4 b = pr[idx];
            float4 w = pa[idx];
            float z;
            z = a.x + b.x; s += w.x * (z > 0.0f ? z : SLOPE * z);
            z = a.y + b.y; s += w.y * (z > 0.0f ? z : SLOPE * z);
            z = a.z + b.z; s += w.z * (z > 0.0f ? z : SLOPE * z);
            z = a.w + b.w; s += w.w * (z > 0.0f ? z : SLOPE * z);
        }
#pragma unroll
        for (int o = 16; o; o >>= 1) s += __shfl_xor_sync(0xFFFFFFFFu, s, o);
        if (lane == 0) s_lg[h * LS_CAP + si] = s;
    }
    __syncthreads();

    if (wid < 4) {
        float* lg = s_lg + wid * LS_CAP;
        float mx = -INFINITY;
        for (int si = lane; si < cnt; si += 32) mx = fmaxf(mx, lg[si]);
#pragma unroll
        for (int o = 16; o; o >>= 1) mx = fmaxf(mx, __shfl_xor_sync(0xFFFFFFFFu, mx, o));
        float den = 0.0f;
        for (int si = lane; si < cnt; si += 32) {
            float ex = expf(lg[si] - mx);
            lg[si] = ex;
            den += ex;
        }
#pragma unroll
        for (int o = 16; o; o >>= 1) den += __shfl_xor_sync(0xFFFFFFFFu, den, o);
        float inv = 1.0f / den;
        for (int si = lane; si < cnt; si += 32)
            d_alpha[(s0 + si) * HH + wid] = lg[si] * inv;
    }
}

// ---------------- stage 5: aggregation ---------------------------------------
__global__ void __launch_bounds__(256)
agg_kernel() {
    __shared__ int   s_src[128];
    __shared__ float s_al[HH][128];
    int n = blockIdx.x, tid = threadIdx.x;
    int s0 = d_rowptr[n], s1 = d_rowptr[n + 1];

    float4 acc[12];
#pragma unroll
    for (int j = 0; j < 12; j++) acc[j] = make_float4(0.f, 0.f, 0.f, 0.f);

    for (int base = s0; base < s1; base += 128) {
        int cnt = min(128, s1 - base);
        __syncthreads();
        if (tid < cnt) {
            s_src[tid] = d_esrc[base + tid];
            float4 a = *(const float4*)(d_alpha + (size_t)(base + tid) * HH);
            s_al[0][tid] = a.x; s_al[1][tid] = a.y;
            s_al[2][tid] = a.z; s_al[3][tid] = a.w;
        }
        __syncthreads();
        for (int s = 0; s < cnt; s++) {
            const float4* row = (const float4*)(d_xl + (size_t)s_src[s] * HF);
            float al0 = s_al[0][s], al1 = s_al[1][s], al2 = s_al[2][s], al3 = s_al[3][s];
#pragma unroll
            for (int j = 0; j < 12; j++) {
                float al = (j < 3) ? al0 : (j < 6) ? al1 : (j < 9) ? al2 : al3;
                float4 v = row[j * 256 + tid];
                acc[j].x += al * v.x;
                acc[j].y += al * v.y;
                acc[j].z += al * v.z;
                acc[j].w += al * v.w;
            }
        }
    }

#pragma unroll
    for (int j = 0; j < 12; j++)
        *(float4*)(d_agg + (size_t)n * HF + (j * 256 + tid) * 4) = acc[j];
}

// ---------------- stage 6: fc2+BN2+residual + FFN (fused) --------------------
__global__ void final_kernel(const float* __restrict__ x,
                             const float* __restrict__ gat_b,
                             const float* __restrict__ fc2W, const float* __restrict__ fc2b,
                             const float* __restrict__ b2g, const float* __restrict__ b2b,
                             const float* __restrict__ b2m, const float* __restrict__ b2v,
                             const float* __restrict__ f1W, const float* __restrict__ f1b,
                             const float* __restrict__ bf1g, const float* __restrict__ bf1b,
                             const float* __restrict__ bf1m, const float* __restrict__ bf1v,
                             const float* __restrict__ f2W, const float* __restrict__ f2b,
                             const float* __restrict__ bf2g, const float* __restrict__ bf2b,
                             const float* __restrict__ bf2m, const float* __restrict__ bf2v,
                             float* __restrict__ out) {
    int n = blockIdx.x;
    int p = blockIdx.y * 256 + threadIdx.x;

    float ch[HH * CC];
#pragma unroll
    for (int h = 0; h < HH; h++)
#pragma unroll
        for (int c = 0; c < CC; c++)
            ch[h * CC + c] = d_agg[(size_t)n * HF + h * FF + c * PIX + p]
                           + gat_b[h * FF + c * PIX + p];

    float gv[CC];
#pragma unroll
    for (int oc = 0; oc < CC; oc++) {
        float t = fc2b[oc];
#pragma unroll
        for (int k = 0; k < HH * CC; k++) t += fc2W[oc * (HH * CC) + k] * ch[k];
        float inv = b2g[oc] * rsqrtf(b2v[oc] + BEPS);
        gv[oc] = t * inv + b2b[oc] - b2m[oc] * inv + x[(size_t)n * FF + oc * PIX + p];
    }
    float f1[CC];
#pragma unroll
    for (int oc = 0; oc < CC; oc++) {
        float t = f1b[oc];
#pragma unroll
        for (int ic = 0; ic < CC; ic++) t += f1W[oc * CC + ic] * gv[ic];
        float inv = bf1g[oc] * rsqrtf(bf1v[oc] + BEPS);
        float val = t * inv + bf1b[oc] - bf1m[oc] * inv;
        f1[oc] = val > 0.0f ? val : 0.0f;
    }
#pragma unroll
    for (int oc = 0; oc < CC; oc++) {
        float t = f2b[oc];
#pragma unroll
        for (int ic = 0; ic < CC; ic++) t += f2W[oc * CC + ic] * f1[ic];
        float inv = bf2g[oc] * rsqrtf(bf2v[oc] + BEPS);
        float val = t * inv + bf2b[oc] - bf2m[oc] * inv;
        out[(size_t)n * FF + oc * PIX + p] = val + gv[oc];
    }
}

// ---------------- launch -----------------------------------------------------
extern "C" void kernel_launch(void* const* d_in, const int* in_sizes, int n_in,
                              void* d_out, int out_size) {
    const float* x     = (const float*)d_in[0];
    const int*   ei    = (const int*)d_in[1];
    const float* fc1W  = (const float*)d_in[2];
    const float* fc1b  = (const float*)d_in[3];
    const float* b1g   = (const float*)d_in[4];
    const float* b1b   = (const float*)d_in[5];
    const float* b1m   = (const float*)d_in[6];
    const float* b1v   = (const float*)d_in[7];
    const float* Wl    = (const float*)d_in[8];
    const float* bl    = (const float*)d_in[9];
    const float* Wr    = (const float*)d_in[10];
    const float* br    = (const float*)d_in[11];
    const float* att   = (const float*)d_in[12];
    const float* gat_b = (const float*)d_in[13];
    const float* fc2W  = (const float*)d_in[14];
    const float* fc2b  = (const float*)d_in[15];
    const float* b2g   = (const float*)d_in[16];
    const float* b2b   = (const float*)d_in[17];
    const float* b2m   = (const float*)d_in[18];
    const float* b2v   = (const float*)d_in[19];
    const float* f1W   = (const float*)d_in[20];
    const float* f1b   = (const float*)d_in[21];
    const float* bf1g  = (const float*)d_in[22];
    const float* bf1b  = (const float*)d_in[23];
    const float* bf1m  = (const float*)d_in[24];
    const float* bf1v  = (const float*)d_in[25];
    const float* f2W   = (const float*)d_in[26];
    const float* f2b   = (const float*)d_in[27];
    const float* bf2g  = (const float*)d_in[28];
    const float* bf2b  = (const float*)d_in[29];
    const float* bf2m  = (const float*)d_in[30];
    const float* bf2v  = (const float*)d_in[31];
    float* out = (float*)d_out;

    cudaFuncSetAttribute(mmagemm_kernel, cudaFuncAttributeMaxDynamicSharedMemorySize, SMEM_TOTAL);
    cudaFuncSetAttribute(logits_softmax_kernel, cudaFuncAttributeMaxDynamicSharedMemorySize, LS_SMEM);

    wconv_kernel<<<dim3((FF * HF) / (256 * 8), 2), 256>>>(Wl, Wr);
    fc1_bn_kernel<<<dim3(NN, 4), 256>>>(x, fc1W, fc1b, b1g, b1b, b1m, b1v);
    csr_kernel<<<1, NN>>>(ei);
    mmagemm_kernel<<<2 * TILES_PER_GEMM, 256, SMEM_TOTAL>>>(bl, br);
    logits_softmax_kernel<<<NN, 256, LS_SMEM>>>(att);
    agg_kernel<<<NN, 256>>>();
    final_kernel<<<dim3(NN, 4), 256>>>(x, gat_b, fc2W, fc2b, b2g, b2b, b2m, b2v,
                                       f1W, f1b, bf1g, bf1b, bf1m, bf1v,
                                       f2W, f2b, bf2g, bf2b, bf2m, bf2v, out);
}